// round 1
// baseline (speedup 1.0000x reference)
#include <cuda_runtime.h>
#include <math.h>

#define BB 2
#define C 128
#define H 192
#define W 192
#define HW (H*W)
#define CHW (C*HW)
#define E 128
#define SWID 24
#define NN 576
#define BF 128
#define NB 256

// ---------------- scratch (static device globals; no allocation) ----------------
__device__ float g_part[BB*NB*2];
__device__ float g_mv[4];
__device__ float g_qk[(size_t)BF*NN*E];   // 37.7 MB
__device__ float g_v [(size_t)BF*NN*C];   // 37.7 MB
__device__ float g_y [(size_t)BB*CHW];    // 37.7 MB
__device__ float g_h1[(size_t)BB*CHW];
__device__ float g_h2[(size_t)BB*CHW];

// ---------------- 4x8 / 4x4 FMA micro-tiles ----------------
#define FMA48(ACC, A4, B0, B1) do{                                   \
  float av_[4] = {(A4).x,(A4).y,(A4).z,(A4).w};                      \
  float bv_[8] = {(B0).x,(B0).y,(B0).z,(B0).w,(B1).x,(B1).y,(B1).z,(B1).w}; \
  _Pragma("unroll") for (int ii_=0; ii_<4; ii_++)                    \
    _Pragma("unroll") for (int jj_=0; jj_<8; jj_++)                  \
      ACC[ii_][jj_] += av_[ii_]*bv_[jj_];                            \
}while(0)

#define FMA44(ACC, A4, B4) do{                                       \
  float av_[4] = {(A4).x,(A4).y,(A4).z,(A4).w};                      \
  float bv_[4] = {(B4).x,(B4).y,(B4).z,(B4).w};                      \
  _Pragma("unroll") for (int ii_=0; ii_<4; ii_++)                    \
    _Pragma("unroll") for (int jj_=0; jj_<4; jj_++)                  \
      ACC[ii_][jj_] += av_[ii_]*bv_[jj_];                            \
}while(0)

// ---------------- LayerNorm stats ----------------
__global__ void ln_partial_kernel(const float* __restrict__ x){
  int b = blockIdx.y;
  const float* xb = x + (size_t)b*CHW;
  float s = 0.f, ss = 0.f;
  for (int i = blockIdx.x*256 + threadIdx.x; i < CHW; i += NB*256){
    float v = xb[i]; s += v; ss += v*v;
  }
  #pragma unroll
  for (int o = 16; o; o >>= 1){
    s  += __shfl_xor_sync(0xffffffffu, s,  o);
    ss += __shfl_xor_sync(0xffffffffu, ss, o);
  }
  __shared__ float rs[8], rss[8];
  int warp = threadIdx.x >> 5, lane = threadIdx.x & 31;
  if (!lane){ rs[warp] = s; rss[warp] = ss; }
  __syncthreads();
  if (!threadIdx.x){
    float a = 0.f, c2 = 0.f;
    #pragma unroll
    for (int i = 0; i < 8; i++){ a += rs[i]; c2 += rss[i]; }
    g_part[(b*NB + blockIdx.x)*2]   = a;
    g_part[(b*NB + blockIdx.x)*2+1] = c2;
  }
}

__global__ void ln_final_kernel(){
  int b = blockIdx.x, t = threadIdx.x;
  float s  = g_part[(b*NB + t)*2];
  float ss = g_part[(b*NB + t)*2+1];
  #pragma unroll
  for (int o = 16; o; o >>= 1){
    s  += __shfl_xor_sync(0xffffffffu, s,  o);
    ss += __shfl_xor_sync(0xffffffffu, ss, o);
  }
  __shared__ float rs[8], rss[8];
  int warp = t >> 5, lane = t & 31;
  if (!lane){ rs[warp] = s; rss[warp] = ss; }
  __syncthreads();
  if (!t){
    float a = 0.f, c2 = 0.f;
    #pragma unroll
    for (int i = 0; i < 8; i++){ a += rs[i]; c2 += rss[i]; }
    float mean = a / (float)CHW;
    float var  = c2 / (float)CHW - mean*mean;
    g_mv[b*2]   = mean;
    g_mv[b*2+1] = rsqrtf(var + 1e-5f);
  }
}

// ---------------- prep: unshuffle + qk projection + row L2-norm ----------------
// smem: ws 128*128 | xt 128*68 (transposed xn tile) | qo 64*132 (staging)
#define PREP_SMEM ((16384 + 8704 + 8448)*4)
__global__ __launch_bounds__(256) void prep_kernel(const float* __restrict__ x,
                                                   const float* __restrict__ wqk){
  int blk = blockIdx.x;                 // 1152 blocks of 64 rows
  int r0  = blk*64;
  int bf  = r0 / NN;                    // 64 | 576, so whole tile in one sub-image
  int b   = bf >> 6, k = bf & 63, dy = k >> 3, dx = k & 7;
  float mean = g_mv[b*2], rstd = g_mv[b*2+1];
  extern __shared__ float sm[];
  float* ws = sm;                 // wqk [c][e]
  float* xt = sm + 16384;         // xn transposed [c][i], pitch 68
  float* qo = sm + 16384 + 8704;  // qk staging [i][e], pitch 132
  int tid = threadIdx.x;

  for (int l = tid; l < 16384; l += 256) ws[l] = wqk[l];

  int n0 = r0 - bf*NN;
  for (int l = tid; l < 8192; l += 256){
    int i = l >> 7, c = l & 127;
    int n  = n0 + i;
    int sh = n / SWID, swp = n - sh*SWID;
    int h  = sh*8 + dy, w = swp*8 + dx;
    float xv = x[(size_t)(b*C + c)*HW + h*W + w];
    g_v[(size_t)(r0 + i)*C + c] = xv;
    xt[c*68 + i] = (xv - mean)*rstd;
  }
  __syncthreads();

  int tx = tid & 15, ty = tid >> 4;
  float acc[4][8] = {};
  const float4* xt4 = (const float4*)xt;
  const float4* ws4 = (const float4*)ws;
  #pragma unroll 4
  for (int c = 0; c < 128; c++){
    float4 a  = xt4[c*17 + ty];
    float4 w0 = ws4[c*32 + tx*2];
    float4 w1 = ws4[c*32 + tx*2 + 1];
    FMA48(acc, a, w0, w1);
  }
  #pragma unroll
  for (int ii = 0; ii < 4; ii++){
    float4 o0 = make_float4(acc[ii][0],acc[ii][1],acc[ii][2],acc[ii][3]);
    float4 o1 = make_float4(acc[ii][4],acc[ii][5],acc[ii][6],acc[ii][7]);
    *(float4*)&qo[(ty*4+ii)*132 + tx*8]     = o0;
    *(float4*)&qo[(ty*4+ii)*132 + tx*8 + 4] = o1;
  }
  __syncthreads();

  int r = tid >> 2, q = tid & 3;
  float ssq = 0.f;
  for (int j = q; j < 128; j += 4){ float v = qo[r*132 + j]; ssq += v*v; }
  ssq += __shfl_xor_sync(0xffffffffu, ssq, 1);
  ssq += __shfl_xor_sync(0xffffffffu, ssq, 2);
  float inv = 1.f/(sqrtf(ssq) + 1e-8f);
  for (int j = q; j < 128; j += 4)
    g_qk[(size_t)(r0 + r)*E + j] = qo[r*132 + j]*inv;
}

// ---------------- attention: scores + softmax + PV + residual shuffle ----------------
// smem: qt 128*68 | kt 128*68 (reused as V 64*132) | sc 64*580
#define ATTN_SMEM ((8704 + 8704 + 37120)*4)
__global__ __launch_bounds__(256) void attn_kernel(const float* __restrict__ x){
  int rt = blockIdx.x;      // row tile 0..8
  int bf = blockIdx.y;      // 0..127
  extern __shared__ float sm[];
  float* qt = sm;
  float* kt = sm + 8704;
  float* sc = sm + 2*8704;
  int tid = threadIdx.x;
  int tx = tid & 15, ty = tid >> 4;
  size_t qbase = (size_t)bf * NN * E;
  int r0 = rt*64;

  for (int l = tid; l < 8192; l += 256){
    int c = l & 127, i = l >> 7;
    qt[c*68 + i] = g_qk[qbase + (size_t)(r0 + i)*E + c];
  }

  const float invsE = 0.08838834764831845f;   // 1/sqrt(128)
  const float4* qt4 = (const float4*)qt;
  const float4* kt4 = (const float4*)kt;

  for (int jt = 0; jt < 9; jt++){
    __syncthreads();
    for (int l = tid; l < 8192; l += 256){
      int c = l & 127, i = l >> 7;
      kt[c*68 + i] = g_qk[qbase + (size_t)(jt*64 + i)*E + c];
    }
    __syncthreads();
    float acc[4][4] = {};
    #pragma unroll 4
    for (int c = 0; c < 128; c++){
      float4 a = qt4[c*17 + ty];
      float4 b = kt4[c*17 + tx];
      FMA44(acc, a, b);
    }
    #pragma unroll
    for (int ii = 0; ii < 4; ii++){
      float4 o;
      o.x = (acc[ii][0] + 1.f)*invsE;
      o.y = (acc[ii][1] + 1.f)*invsE;
      o.z = (acc[ii][2] + 1.f)*invsE;
      o.w = (acc[ii][3] + 1.f)*invsE;
      *(float4*)&sc[(ty*4+ii)*580 + jt*64 + tx*4] = o;
    }
  }
  __syncthreads();

  { // softmax: 4 lanes per row
    int r = tid >> 2, q = tid & 3;
    float* row = sc + r*580;
    float m = -1e30f;
    for (int j = q; j < NN; j += 4) m = fmaxf(m, row[j]);
    m = fmaxf(m, __shfl_xor_sync(0xffffffffu, m, 1));
    m = fmaxf(m, __shfl_xor_sync(0xffffffffu, m, 2));
    float s = 0.f;
    for (int j = q; j < NN; j += 4){ float e = __expf(row[j]-m); row[j] = e; s += e; }
    s += __shfl_xor_sync(0xffffffffu, s, 1);
    s += __shfl_xor_sync(0xffffffffu, s, 2);
    float inv = 1.f/s;
    for (int j = q; j < NN; j += 4) row[j] *= inv;
  }

  float acc2[4][8] = {};
  float* vs = kt;                           // reuse (64*132 <= 128*68)
  const float4* vs4 = (const float4*)vs;
  size_t vbase = (size_t)bf * NN * C;
  for (int mt = 0; mt < 9; mt++){
    __syncthreads();
    for (int l = tid; l < 8192; l += 256){
      int c = l & 127, m = l >> 7;
      vs[m*132 + c] = g_v[vbase + (size_t)(mt*64 + m)*C + c];
    }
    __syncthreads();
    #pragma unroll 2
    for (int m = 0; m < 64; m++){
      float4 b0 = vs4[m*33 + tx*2];
      float4 b1 = vs4[m*33 + tx*2 + 1];
      #pragma unroll
      for (int ii = 0; ii < 4; ii++){
        float p = sc[(ty*4+ii)*580 + mt*64 + m];
        acc2[ii][0] += p*b0.x; acc2[ii][1] += p*b0.y;
        acc2[ii][2] += p*b0.z; acc2[ii][3] += p*b0.w;
        acc2[ii][4] += p*b1.x; acc2[ii][5] += p*b1.y;
        acc2[ii][6] += p*b1.z; acc2[ii][7] += p*b1.w;
      }
    }
  }

  int b = bf >> 6, k = bf & 63, dy = k >> 3, dx = k & 7;
  #pragma unroll
  for (int ii = 0; ii < 4; ii++){
    int n  = r0 + ty*4 + ii;
    int sh = n / SWID, swp = n - sh*SWID;
    int h  = sh*8 + dy, w = swp*8 + dx;
    #pragma unroll
    for (int jj = 0; jj < 8; jj++){
      int c = tx*8 + jj;
      size_t gi = (size_t)(b*C + c)*HW + (size_t)h*W + w;
      g_y[gi] = x[gi] + acc2[ii][jj];
    }
  }
}

// ---------------- 3x3 dilated conv (dil=2, pad=2) + ReLU ----------------
// smem: ins 32*20*20 | ws 288*36
#define CONV_SMEM ((12800 + 10368)*4)
__global__ __launch_bounds__(256) void conv3x3_kernel(const float* __restrict__ in,
                                                      const float* __restrict__ wt,
                                                      const float* __restrict__ bias,
                                                      float* __restrict__ out){
  int txle = blockIdx.x*16, tyle = blockIdx.y*16;
  int z = blockIdx.z; int b = z >> 2; int cog = z & 3;
  extern __shared__ float sm[];
  float* ins = sm;            // [ci][yy][xx], 32*400
  float* ws  = sm + 12800;    // [ci*9+kk][co], pitch 36
  int tid = threadIdx.x;
  int cog_t = tid >> 6;       // out-channel sub-group of 8 (uniform per warp)
  int pxg   = tid & 63;
  int x0 = (pxg & 3)*4, y0 = pxg >> 2;
  float acc[8][4] = {};

  for (int ch = 0; ch < 4; ch++){
    __syncthreads();
    for (int l = tid; l < 12800; l += 256){
      int ci = l / 400, r = l - ci*400, yy = r / 20, xx = r - yy*20;
      int gy = tyle - 2 + yy, gx = txle - 2 + xx;
      float v = 0.f;
      if (gy >= 0 && gy < H && gx >= 0 && gx < W)
        v = in[(size_t)(b*C + ch*32 + ci)*HW + gy*W + gx];
      ins[l] = v;
    }
    for (int l = tid; l < 9216; l += 256){
      int co_l = l / 288, r = l - co_l*288;   // r = ci*9+kk
      ws[r*36 + co_l] = wt[(size_t)(cog*32 + co_l)*(C*9) + ch*288 + r];
    }
    __syncthreads();
    for (int ci = 0; ci < 32; ci++){
      #pragma unroll
      for (int ky = 0; ky < 3; ky++){
        #pragma unroll
        for (int kx = 0; kx < 3; kx++){
          int kk = ky*3 + kx;
          const float4* w4 = (const float4*)&ws[(ci*9+kk)*36];
          float4 w0 = w4[cog_t*2], w1 = w4[cog_t*2+1];
          const float* ip = &ins[ci*400 + (y0 + 2*ky)*20 + x0 + 2*kx];
          #pragma unroll
          for (int p = 0; p < 4; p++){
            float iv = ip[p];
            acc[0][p] += iv*w0.x; acc[1][p] += iv*w0.y;
            acc[2][p] += iv*w0.z; acc[3][p] += iv*w0.w;
            acc[4][p] += iv*w1.x; acc[5][p] += iv*w1.y;
            acc[6][p] += iv*w1.z; acc[7][p] += iv*w1.w;
          }
        }
      }
    }
  }

  int gy = tyle + y0, gx = txle + x0;
  #pragma unroll
  for (int q = 0; q < 8; q++){
    int co = cog*32 + cog_t*8 + q;
    float bv = bias[co];
    float4 o;
    o.x = fmaxf(acc[q][0] + bv, 0.f);
    o.y = fmaxf(acc[q][1] + bv, 0.f);
    o.z = fmaxf(acc[q][2] + bv, 0.f);
    o.w = fmaxf(acc[q][3] + bv, 0.f);
    *(float4*)&out[(size_t)(b*C + co)*HW + (size_t)gy*W + gx] = o;
  }
}

// ---------------- 1x1 conv + bias + residual ----------------
// smem: w3t 128*132 | hs 128*68
#define C1_SMEM ((16896 + 8704)*4)
__global__ __launch_bounds__(256) void conv1x1_res_kernel(const float* __restrict__ hin,
                                                          const float* __restrict__ w3,
                                                          const float* __restrict__ b3,
                                                          const float* __restrict__ x,
                                                          float* __restrict__ out){
  int blk = blockIdx.x;
  int b   = blk / (HW/64);
  int hw0 = (blk - b*(HW/64))*64;
  extern __shared__ float sm[];
  float* w3t = sm;            // [ci][co], pitch 132
  float* hs  = sm + 16896;    // [ci][px], pitch 68
  int tid = threadIdx.x;
  for (int l = tid; l < 16384; l += 256){
    int co = l >> 7, ci = l & 127;
    w3t[ci*132 + co] = w3[l];
  }
  for (int l = tid; l < 8192; l += 256){
    int ci = l >> 6, p = l & 63;
    hs[ci*68 + p] = hin[(size_t)(b*C + ci)*HW + hw0 + p];
  }
  __syncthreads();

  int tx = tid & 15, ty = tid >> 4;
  float acc[4][8] = {};   // [px][co]
  const float4* hs4 = (const float4*)hs;
  const float4* w4  = (const float4*)w3t;
  #pragma unroll 4
  for (int ci = 0; ci < 128; ci++){
    float4 a  = hs4[ci*17 + tx];
    float4 w0 = w4[ci*33 + ty*2];
    float4 w1 = w4[ci*33 + ty*2 + 1];
    FMA48(acc, a, w0, w1);
  }
  #pragma unroll
  for (int q = 0; q < 8; q++){
    int co = ty*8 + q;
    float bv = b3[co];
    size_t gi = (size_t)(b*C + co)*HW + hw0 + tx*4;
    float4 xo = *(const float4*)&x[gi];
    float4 o;
    o.x = xo.x + acc[0][q] + bv;
    o.y = xo.y + acc[1][q] + bv;
    o.z = xo.z + acc[2][q] + bv;
    o.w = xo.w + acc[3][q] + bv;
    *(float4*)&out[gi] = o;
  }
}

// ---------------- launch ----------------
extern "C" void kernel_launch(void* const* d_in, const int* in_sizes, int n_in,
                              void* d_out, int out_size){
  const float* x   = (const float*)d_in[0];
  const float* wqk = (const float*)d_in[1];
  const float* w1  = (const float*)d_in[2];
  const float* b1  = (const float*)d_in[3];
  const float* w2  = (const float*)d_in[4];
  const float* b2  = (const float*)d_in[5];
  const float* w3  = (const float*)d_in[6];
  const float* b3  = (const float*)d_in[7];
  float* out = (float*)d_out;

  cudaFuncSetAttribute(prep_kernel,       cudaFuncAttributeMaxDynamicSharedMemorySize, PREP_SMEM);
  cudaFuncSetAttribute(attn_kernel,       cudaFuncAttributeMaxDynamicSharedMemorySize, ATTN_SMEM);
  cudaFuncSetAttribute(conv3x3_kernel,    cudaFuncAttributeMaxDynamicSharedMemorySize, CONV_SMEM);
  cudaFuncSetAttribute(conv1x1_res_kernel,cudaFuncAttributeMaxDynamicSharedMemorySize, C1_SMEM);

  void *py_, *ph1_, *ph2_;
  cudaGetSymbolAddress(&py_,  g_y);
  cudaGetSymbolAddress(&ph1_, g_h1);
  cudaGetSymbolAddress(&ph2_, g_h2);
  float* py  = (float*)py_;
  float* ph1 = (float*)ph1_;
  float* ph2 = (float*)ph2_;

  ln_partial_kernel<<<dim3(NB, BB), 256>>>(x);
  ln_final_kernel<<<BB, 256>>>();
  prep_kernel<<<(BF*NN)/64, 256, PREP_SMEM>>>(x, wqk);
  attn_kernel<<<dim3(9, BF), 256, ATTN_SMEM>>>(x);
  conv3x3_kernel<<<dim3(12,12,8), 256, CONV_SMEM>>>(py,  w1, b1, ph1);
  conv3x3_kernel<<<dim3(12,12,8), 256, CONV_SMEM>>>(ph1, w2, b2, ph2);
  conv1x1_res_kernel<<<(BB*HW)/64, 256, C1_SMEM>>>(ph2, w3, b3, x, out);
}

// round 3
// speedup vs baseline: 1.2313x; 1.2313x over previous
#include <cuda_runtime.h>
#include <math.h>

#define BB 2
#define C 128
#define H 192
#define W 192
#define HW (H*W)
#define CHW (C*HW)
#define E 128
#define SWID 24
#define NN 576
#define BF 128
#define NB 256

typedef unsigned long long ull;

// ---------------- packed f32x2 helpers ----------------
__device__ __forceinline__ ull pk2(float v){
  ull r; asm("mov.b64 %0, {%1, %1};" : "=l"(r) : "f"(v)); return r;
}
__device__ __forceinline__ void ffma2(ull &d, ull a, ull b){
  asm("fma.rn.f32x2 %0, %1, %2, %3;" : "=l"(d) : "l"(a), "l"(b), "l"(d));
}
__device__ __forceinline__ float2 upk(ull v){
  float2 f; asm("mov.b64 {%0, %1}, %2;" : "=f"(f.x), "=f"(f.y) : "l"(v)); return f;
}
__device__ __forceinline__ ull d2u(double d){ return __double_as_longlong(d); }

// ---------------- scratch (static device globals; no allocation) ----------------
__device__ float g_part[BB*NB*2];
__device__ float g_mv[4];
__device__ float g_qk[(size_t)BF*NN*E];
__device__ float g_v [(size_t)BF*NN*C];
__device__ float g_y [(size_t)BB*CHW];
__device__ float g_h1[(size_t)BB*CHW];
__device__ float g_h2[(size_t)BB*CHW];

// ---------------- LayerNorm stats ----------------
__global__ void ln_partial_kernel(const float* __restrict__ x){
  int b = blockIdx.y;
  const float* xb = x + (size_t)b*CHW;
  float s = 0.f, ss = 0.f;
  for (int i = blockIdx.x*256 + threadIdx.x; i < CHW; i += NB*256){
    float v = xb[i]; s += v; ss += v*v;
  }
  #pragma unroll
  for (int o = 16; o; o >>= 1){
    s  += __shfl_xor_sync(0xffffffffu, s,  o);
    ss += __shfl_xor_sync(0xffffffffu, ss, o);
  }
  __shared__ float rs[8], rss[8];
  int warp = threadIdx.x >> 5, lane = threadIdx.x & 31;
  if (!lane){ rs[warp] = s; rss[warp] = ss; }
  __syncthreads();
  if (!threadIdx.x){
    float a = 0.f, c2 = 0.f;
    #pragma unroll
    for (int i = 0; i < 8; i++){ a += rs[i]; c2 += rss[i]; }
    g_part[(b*NB + blockIdx.x)*2]   = a;
    g_part[(b*NB + blockIdx.x)*2+1] = c2;
  }
}

__global__ void ln_final_kernel(){
  int b = blockIdx.x, t = threadIdx.x;
  float s  = g_part[(b*NB + t)*2];
  float ss = g_part[(b*NB + t)*2+1];
  #pragma unroll
  for (int o = 16; o; o >>= 1){
    s  += __shfl_xor_sync(0xffffffffu, s,  o);
    ss += __shfl_xor_sync(0xffffffffu, ss, o);
  }
  __shared__ float rs[8], rss[8];
  int warp = t >> 5, lane = t & 31;
  if (!lane){ rs[warp] = s; rss[warp] = ss; }
  __syncthreads();
  if (!t){
    float a = 0.f, c2 = 0.f;
    #pragma unroll
    for (int i = 0; i < 8; i++){ a += rs[i]; c2 += rss[i]; }
    float mean = a / (float)CHW;
    float var  = c2 / (float)CHW - mean*mean;
    g_mv[b*2]   = mean;
    g_mv[b*2+1] = rsqrtf(var + 1e-5f);
  }
}

// ---------------- prep: unshuffle + qk projection + row L2-norm ----------------
#define PREP_SMEM ((16384 + 8704 + 8448)*4)
__global__ __launch_bounds__(256) void prep_kernel(const float* __restrict__ x,
                                                   const float* __restrict__ wqk){
  int blk = blockIdx.x;
  int r0  = blk*64;
  int bf  = r0 / NN;
  int b   = bf >> 6, k = bf & 63, dy = k >> 3, dx = k & 7;
  float mean = g_mv[b*2], rstd = g_mv[b*2+1];
  extern __shared__ float sm[];
  float* ws = sm;                 // wqk [c][e]
  float* xt = sm + 16384;         // xn transposed [c][i], pitch 68
  float* qo = sm + 16384 + 8704;  // qk staging [i][e], pitch 132
  int tid = threadIdx.x;

  for (int l = tid; l < 16384; l += 256) ws[l] = wqk[l];

  int n0 = r0 - bf*NN;
  for (int l = tid; l < 8192; l += 256){
    int i = l >> 7, c = l & 127;
    int n  = n0 + i;
    int sh = n / SWID, swp = n - sh*SWID;
    int h  = sh*8 + dy, w = swp*8 + dx;
    float xv = x[(size_t)(b*C + c)*HW + h*W + w];
    g_v[(size_t)(r0 + i)*C + c] = xv;
    xt[c*68 + i] = (xv - mean)*rstd;
  }
  __syncthreads();

  int tx = tid & 15, ty = tid >> 4;
  ull acc[4][4] = {};      // [row ii][e-pair]
  #pragma unroll 2
  for (int c = 0; c < 128; c++){
    float4 a = *(const float4*)&xt[c*68 + ty*4];
    const double2* wp = (const double2*)&ws[c*128 + tx*8];
    double2 wA = wp[0], wB = wp[1];
    ull w0 = d2u(wA.x), w1 = d2u(wA.y), w2 = d2u(wB.x), w3 = d2u(wB.y);
    ull a0 = pk2(a.x), a1 = pk2(a.y), a2 = pk2(a.z), a3 = pk2(a.w);
    ffma2(acc[0][0],a0,w0); ffma2(acc[0][1],a0,w1); ffma2(acc[0][2],a0,w2); ffma2(acc[0][3],a0,w3);
    ffma2(acc[1][0],a1,w0); ffma2(acc[1][1],a1,w1); ffma2(acc[1][2],a1,w2); ffma2(acc[1][3],a1,w3);
    ffma2(acc[2][0],a2,w0); ffma2(acc[2][1],a2,w1); ffma2(acc[2][2],a2,w2); ffma2(acc[2][3],a2,w3);
    ffma2(acc[3][0],a3,w0); ffma2(acc[3][1],a3,w1); ffma2(acc[3][2],a3,w2); ffma2(acc[3][3],a3,w3);
  }
  #pragma unroll
  for (int ii = 0; ii < 4; ii++){
    double2 s0 = make_double2(__longlong_as_double(acc[ii][0]), __longlong_as_double(acc[ii][1]));
    double2 s1 = make_double2(__longlong_as_double(acc[ii][2]), __longlong_as_double(acc[ii][3]));
    *(double2*)&qo[(ty*4+ii)*132 + tx*8]     = s0;
    *(double2*)&qo[(ty*4+ii)*132 + tx*8 + 4] = s1;
  }
  __syncthreads();

  int r = tid >> 2, q = tid & 3;
  float ssq = 0.f;
  for (int j = q; j < 128; j += 4){ float v = qo[r*132 + j]; ssq += v*v; }
  ssq += __shfl_xor_sync(0xffffffffu, ssq, 1);
  ssq += __shfl_xor_sync(0xffffffffu, ssq, 2);
  float inv = 1.f/(sqrtf(ssq) + 1e-8f);
  for (int j = q; j < 128; j += 4)
    g_qk[(size_t)(r0 + r)*E + j] = qo[r*132 + j]*inv;
}

// ---------------- attention: flash-style, no-max softmax ----------------
// smem: qt 128*68 | kv 128*68 (K then V 64*132) | pt 64*68
#define ATTN_SMEM ((8704 + 8704 + 4352)*4)
__global__ __launch_bounds__(256,2) void attn_kernel(const float* __restrict__ x){
  int rt = blockIdx.x;      // row tile 0..8
  int bf = blockIdx.y;      // 0..127
  extern __shared__ float sm[];
  float* qt = sm;           // [c][i] pitch 68
  float* kv = sm + 8704;    // K [c][j] pitch 68 ; V [m][c] pitch 132
  float* pt = sm + 17408;   // P [m][row] pitch 68
  int tid = threadIdx.x;
  int tx = tid & 15, ty = tid >> 4;
  size_t qbase = (size_t)bf * NN * E;
  size_t vbase = (size_t)bf * NN * C;
  int r0 = rt*64;

  for (int l = tid; l < 8192; l += 256){
    int c = l & 127, i = l >> 7;
    qt[c*68 + i] = g_qk[qbase + (size_t)(r0 + i)*E + c];
  }

  const float invsE = 0.08838834764831845f;   // 1/sqrt(128); constants cancel in softmax
  ull acc2[4][4] = {};                        // [row ii][c-pair]
  float rsum[4] = {0.f,0.f,0.f,0.f};

  for (int jt = 0; jt < 9; jt++){
    __syncthreads();
    for (int l = tid; l < 8192; l += 256){
      int c = l & 127, j = l >> 7;
      kv[c*68 + j] = g_qk[qbase + (size_t)(jt*64 + j)*E + c];
    }
    __syncthreads();

    ull sa[2][4] = {};                        // row pairs x 4 cols
    #pragma unroll 2
    for (int c = 0; c < 128; c++){
      double2 qp = *(const double2*)&qt[c*68 + ty*4];
      float4  kq = *(const float4*)&kv[c*68 + tx*4];
      ull a01 = d2u(qp.x), a23 = d2u(qp.y);
      ull b0 = pk2(kq.x), b1 = pk2(kq.y), b2 = pk2(kq.z), b3 = pk2(kq.w);
      ffma2(sa[0][0],a01,b0); ffma2(sa[0][1],a01,b1); ffma2(sa[0][2],a01,b2); ffma2(sa[0][3],a01,b3);
      ffma2(sa[1][0],a23,b0); ffma2(sa[1][1],a23,b1); ffma2(sa[1][2],a23,b2); ffma2(sa[1][3],a23,b3);
    }
    #pragma unroll
    for (int i2 = 0; i2 < 2; i2++){
      #pragma unroll
      for (int j = 0; j < 4; j++){
        float2 v = upk(sa[i2][j]);
        float p0 = __expf(v.x*invsE);
        float p1 = __expf(v.y*invsE);
        rsum[2*i2]   += p0;
        rsum[2*i2+1] += p1;
        *(float2*)&pt[(tx*4+j)*68 + ty*4 + 2*i2] = make_float2(p0, p1);
      }
    }
    __syncthreads();
    for (int l = tid; l < 8192; l += 256){
      int c = l & 127, m = l >> 7;
      kv[m*132 + c] = g_v[vbase + (size_t)(jt*64 + m)*C + c];
    }
    __syncthreads();

    #pragma unroll 2
    for (int m = 0; m < 64; m++){
      double2 v01 = *(const double2*)&kv[m*132 + tx*8];
      double2 v23 = *(const double2*)&kv[m*132 + tx*8 + 4];
      float4  p4  = *(const float4*)&pt[m*68 + ty*4];
      ull vb0 = d2u(v01.x), vb1 = d2u(v01.y), vb2 = d2u(v23.x), vb3 = d2u(v23.y);
      ull pb0 = pk2(p4.x), pb1 = pk2(p4.y), pb2 = pk2(p4.z), pb3 = pk2(p4.w);
      ffma2(acc2[0][0],pb0,vb0); ffma2(acc2[0][1],pb0,vb1); ffma2(acc2[0][2],pb0,vb2); ffma2(acc2[0][3],pb0,vb3);
      ffma2(acc2[1][0],pb1,vb0); ffma2(acc2[1][1],pb1,vb1); ffma2(acc2[1][2],pb1,vb2); ffma2(acc2[1][3],pb1,vb3);
      ffma2(acc2[2][0],pb2,vb0); ffma2(acc2[2][1],pb2,vb1); ffma2(acc2[2][2],pb2,vb2); ffma2(acc2[2][3],pb2,vb3);
      ffma2(acc2[3][0],pb3,vb0); ffma2(acc2[3][1],pb3,vb1); ffma2(acc2[3][2],pb3,vb2); ffma2(acc2[3][3],pb3,vb3);
    }
  }

  // reduce row sums across tx lanes (offsets 1,2,4,8 stay in the 16-lane half)
  #pragma unroll
  for (int i = 0; i < 4; i++){
    float s = rsum[i];
    s += __shfl_xor_sync(0xffffffffu, s, 1);
    s += __shfl_xor_sync(0xffffffffu, s, 2);
    s += __shfl_xor_sync(0xffffffffu, s, 4);
    s += __shfl_xor_sync(0xffffffffu, s, 8);
    rsum[i] = 1.f/s;
  }

  int b = bf >> 6, kk = bf & 63, dy = kk >> 3, dx = kk & 7;
  #pragma unroll
  for (int ii = 0; ii < 4; ii++){
    int n  = r0 + ty*4 + ii;
    int sh = n / SWID, swp = n - sh*SWID;
    int h  = sh*8 + dy, w = swp*8 + dx;
    size_t base = (size_t)b*CHW + (size_t)h*W + w;
    float inv = rsum[ii];
    #pragma unroll
    for (int jp = 0; jp < 4; jp++){
      float2 v = upk(acc2[ii][jp]);
      size_t gi = base + (size_t)(tx*8 + 2*jp)*HW;
      g_y[gi]    = x[gi]    + v.x*inv;
      g_y[gi+HW] = x[gi+HW] + v.y*inv;
    }
  }
}

// ---------------- 3x3 dilated conv (dil=2, pad=2) + ReLU ----------------
#define CONV_SMEM ((12800 + 10368)*4)
__global__ __launch_bounds__(256,2) void conv3x3_kernel(const float* __restrict__ in,
                                                        const float* __restrict__ wt,
                                                        const float* __restrict__ bias,
                                                        float* __restrict__ out){
  int txle = blockIdx.x*16, tyle = blockIdx.y*16;
  int z = blockIdx.z; int b = z >> 2; int cog = z & 3;
  extern __shared__ float sm[];
  float* ins = sm;            // [ci][yy][xx], 32*400
  float* ws  = sm + 12800;    // [ci*9+kk][co], pitch 36
  int tid = threadIdx.x;
  int cog_t = tid >> 6;
  int pxg   = tid & 63;
  int x0 = (pxg & 3)*4, y0 = pxg >> 2;
  ull acc[4][4] = {};         // [co-pair][p]

  for (int ch = 0; ch < 4; ch++){
    __syncthreads();
    for (int l = tid; l < 12800; l += 256){
      int ci = l / 400, r = l - ci*400, yy = r / 20, xx = r - yy*20;
      int gy = tyle - 2 + yy, gx = txle - 2 + xx;
      float v = 0.f;
      if (gy >= 0 && gy < H && gx >= 0 && gx < W)
        v = in[(size_t)(b*C + ch*32 + ci)*HW + gy*W + gx];
      ins[l] = v;
    }
    for (int l = tid; l < 9216; l += 256){
      int co_l = l / 288, r = l - co_l*288;
      ws[r*36 + co_l] = wt[(size_t)(cog*32 + co_l)*(C*9) + ch*288 + r];
    }
    __syncthreads();
    for (int ci = 0; ci < 32; ci++){
      const float* ip   = &ins[ci*400 + y0*20 + x0];
      const float* wrow = &ws[(ci*9)*36 + cog_t*8];
      #pragma unroll
      for (int ky = 0; ky < 3; ky++){
        float4 ra = *(const float4*)(ip + ky*40);
        float4 rb = *(const float4*)(ip + ky*40 + 4);
        ull bc0 = pk2(ra.x), bc1 = pk2(ra.y), bc2 = pk2(ra.z), bc3 = pk2(ra.w);
        ull bc4 = pk2(rb.x), bc5 = pk2(rb.y), bc6 = pk2(rb.z), bc7 = pk2(rb.w);
        ull bc[8] = {bc0,bc1,bc2,bc3,bc4,bc5,bc6,bc7};
        #pragma unroll
        for (int kx = 0; kx < 3; kx++){
          const double2* wp = (const double2*)(wrow + (ky*3+kx)*36);
          double2 wA = wp[0], wB = wp[1];
          ull w0 = d2u(wA.x), w1 = d2u(wA.y), w2 = d2u(wB.x), w3 = d2u(wB.y);
          #pragma unroll
          for (int p = 0; p < 4; p++){
            ull bv = bc[p + 2*kx];
            ffma2(acc[0][p], bv, w0);
            ffma2(acc[1][p], bv, w1);
            ffma2(acc[2][p], bv, w2);
            ffma2(acc[3][p], bv, w3);
          }
        }
      }
    }
  }

  int gy = tyle + y0, gx = txle + x0;
  #pragma unroll
  for (int cp = 0; cp < 4; cp++){
    float2 o0 = upk(acc[cp][0]), o1 = upk(acc[cp][1]);
    float2 o2 = upk(acc[cp][2]), o3 = upk(acc[cp][3]);
    int coA = cog*32 + cog_t*8 + 2*cp;
    float bA = bias[coA], bB = bias[coA+1];
    float4 qa = make_float4(fmaxf(o0.x+bA,0.f), fmaxf(o1.x+bA,0.f),
                            fmaxf(o2.x+bA,0.f), fmaxf(o3.x+bA,0.f));
    float4 qb = make_float4(fmaxf(o0.y+bB,0.f), fmaxf(o1.y+bB,0.f),
                            fmaxf(o2.y+bB,0.f), fmaxf(o3.y+bB,0.f));
    *(float4*)&out[(size_t)(b*C + coA  )*HW + (size_t)gy*W + gx] = qa;
    *(float4*)&out[(size_t)(b*C + coA+1)*HW + (size_t)gy*W + gx] = qb;
  }
}

// ---------------- 1x1 conv + bias + residual ----------------
#define C1_SMEM ((16896 + 8704)*4)
__global__ __launch_bounds__(256) void conv1x1_res_kernel(const float* __restrict__ hin,
                                                          const float* __restrict__ w3,
                                                          const float* __restrict__ b3,
                                                          const float* __restrict__ x,
                                                          float* __restrict__ out){
  int blk = blockIdx.x;
  int b   = blk / (HW/64);
  int hw0 = (blk - b*(HW/64))*64;
  extern __shared__ float sm[];
  float* w3t = sm;            // [ci][co], pitch 132
  float* hs  = sm + 16896;    // [ci][px], pitch 68
  int tid = threadIdx.x;
  for (int l = tid; l < 16384; l += 256){
    int co = l >> 7, ci = l & 127;
    w3t[ci*132 + co] = w3[l];
  }
  for (int l = tid; l < 8192; l += 256){
    int ci = l >> 6, p = l & 63;
    hs[ci*68 + p] = hin[(size_t)(b*C + ci)*HW + hw0 + p];
  }
  __syncthreads();

  int tx = tid & 15, ty = tid >> 4;
  ull acc[4][4] = {};   // [p][co-pair]
  #pragma unroll 2
  for (int ci = 0; ci < 128; ci++){
    float4 a = *(const float4*)&hs[ci*68 + tx*4];
    const double2* wp = (const double2*)&w3t[ci*132 + ty*8];
    double2 wA = wp[0], wB = wp[1];
    ull w0 = d2u(wA.x), w1 = d2u(wA.y), w2 = d2u(wB.x), w3v = d2u(wB.y);
    ull a0 = pk2(a.x), a1 = pk2(a.y), a2 = pk2(a.z), a3 = pk2(a.w);
    ffma2(acc[0][0],a0,w0); ffma2(acc[0][1],a0,w1); ffma2(acc[0][2],a0,w2); ffma2(acc[0][3],a0,w3v);
    ffma2(acc[1][0],a1,w0); ffma2(acc[1][1],a1,w1); ffma2(acc[1][2],a1,w2); ffma2(acc[1][3],a1,w3v);
    ffma2(acc[2][0],a2,w0); ffma2(acc[2][1],a2,w1); ffma2(acc[2][2],a2,w2); ffma2(acc[2][3],a2,w3v);
    ffma2(acc[3][0],a3,w0); ffma2(acc[3][1],a3,w1); ffma2(acc[3][2],a3,w2); ffma2(acc[3][3],a3,w3v);
  }
  #pragma unroll
  for (int cp = 0; cp < 4; cp++){
    float2 u0 = upk(acc[0][cp]), u1 = upk(acc[1][cp]);
    float2 u2 = upk(acc[2][cp]), u3 = upk(acc[3][cp]);
    int coA = ty*8 + 2*cp;
    float bA = b3[coA], bB = b3[coA+1];
    size_t giA = (size_t)(b*C + coA)*HW + hw0 + tx*4;
    size_t giB = giA + HW;
    float4 xa = *(const float4*)&x[giA];
    float4 xb = *(const float4*)&x[giB];
    *(float4*)&out[giA] = make_float4(xa.x+u0.x+bA, xa.y+u1.x+bA, xa.z+u2.x+bA, xa.w+u3.x+bA);
    *(float4*)&out[giB] = make_float4(xb.x+u0.y+bB, xb.y+u1.y+bB, xb.z+u2.y+bB, xb.w+u3.y+bB);
  }
}

// ---------------- launch ----------------
extern "C" void kernel_launch(void* const* d_in, const int* in_sizes, int n_in,
                              void* d_out, int out_size){
  const float* x   = (const float*)d_in[0];
  const float* wqk = (const float*)d_in[1];
  const float* w1  = (const float*)d_in[2];
  const float* b1  = (const float*)d_in[3];
  const float* w2  = (const float*)d_in[4];
  const float* b2  = (const float*)d_in[5];
  const float* w3  = (const float*)d_in[6];
  const float* b3  = (const float*)d_in[7];
  float* out = (float*)d_out;

  cudaFuncSetAttribute(prep_kernel,        cudaFuncAttributeMaxDynamicSharedMemorySize, PREP_SMEM);
  cudaFuncSetAttribute(attn_kernel,        cudaFuncAttributeMaxDynamicSharedMemorySize, ATTN_SMEM);
  cudaFuncSetAttribute(conv3x3_kernel,     cudaFuncAttributeMaxDynamicSharedMemorySize, CONV_SMEM);
  cudaFuncSetAttribute(conv1x1_res_kernel, cudaFuncAttributeMaxDynamicSharedMemorySize, C1_SMEM);

  void *py_, *ph1_, *ph2_;
  cudaGetSymbolAddress(&py_,  g_y);
  cudaGetSymbolAddress(&ph1_, g_h1);
  cudaGetSymbolAddress(&ph2_, g_h2);
  float* py  = (float*)py_;
  float* ph1 = (float*)ph1_;
  float* ph2 = (float*)ph2_;

  ln_partial_kernel<<<dim3(NB, BB), 256>>>(x);
  ln_final_kernel<<<BB, 256>>>();
  prep_kernel<<<(BF*NN)/64, 256, PREP_SMEM>>>(x, wqk);
  attn_kernel<<<dim3(9, BF), 256, ATTN_SMEM>>>(x);
  conv3x3_kernel<<<dim3(12,12,8), 256, CONV_SMEM>>>(py,  w1, b1, ph1);
  conv3x3_kernel<<<dim3(12,12,8), 256, CONV_SMEM>>>(ph1, w2, b2, ph2);
  conv1x1_res_kernel<<<(BB*HW)/64, 256, C1_SMEM>>>(ph2, w3, b3, x, out);
}

// round 5
// speedup vs baseline: 1.9135x; 1.5541x over previous
#include <cuda_runtime.h>
#include <cuda_bf16.h>
#include <math.h>
#include <stdint.h>

#define BB 2
#define C 128
#define H 192
#define W 192
#define HW (H*W)
#define CHW (C*HW)
#define E 128
#define SWID 24
#define NN 576
#define BF 128
#define NB 256

typedef unsigned long long ull;

// ---------------- packed f32x2 helpers (scalar conv path) ----------------
__device__ __forceinline__ ull pk2(float v){
  ull r; asm("mov.b64 %0, {%1, %1};" : "=l"(r) : "f"(v)); return r;
}
__device__ __forceinline__ void ffma2(ull &d, ull a, ull b){
  asm("fma.rn.f32x2 %0, %1, %2, %3;" : "=l"(d) : "l"(a), "l"(b), "l"(d));
}
__device__ __forceinline__ float2 upk(ull v){
  float2 f; asm("mov.b64 {%0, %1}, %2;" : "=f"(f.x), "=f"(f.y) : "l"(v)); return f;
}
__device__ __forceinline__ ull d2u(double d){ return __double_as_longlong(d); }

// ---------------- mma.sync helpers (base PTX, compute_103-safe) ----------------
__device__ __forceinline__ uint32_t s2u(const void* p){
  uint32_t a;
  asm("{ .reg .u64 t; cvta.to.shared.u64 t, %1; cvt.u32.u64 %0, t; }" : "=r"(a) : "l"(p));
  return a;
}
__device__ __forceinline__ void cp16(uint32_t d, const void* g){
  asm volatile("cp.async.cg.shared.global [%0], [%1], 16;" :: "r"(d), "l"(g));
}
#define CP_COMMIT() asm volatile("cp.async.commit_group;" ::: "memory")

__device__ __forceinline__ void ldsm4(uint32_t* r, uint32_t addr){
  asm volatile("ldmatrix.sync.aligned.m8n8.x4.shared.b16 {%0,%1,%2,%3}, [%4];"
    : "=r"(r[0]),"=r"(r[1]),"=r"(r[2]),"=r"(r[3]) : "r"(addr));
}
__device__ __forceinline__ void mma_bf16(float* c, const uint32_t* a, uint32_t b0, uint32_t b1){
  asm volatile("mma.sync.aligned.m16n8k16.row.col.f32.bf16.bf16.f32 "
    "{%0,%1,%2,%3}, {%4,%5,%6,%7}, {%8,%9}, {%0,%1,%2,%3};"
    : "+f"(c[0]),"+f"(c[1]),"+f"(c[2]),"+f"(c[3])
    : "r"(a[0]),"r"(a[1]),"r"(a[2]),"r"(a[3]), "r"(b0),"r"(b1));
}
__device__ __forceinline__ uint32_t packbf(float lo, float hi){
  uint32_t d; asm("cvt.rn.bf16x2.f32 %0, %1, %2;" : "=r"(d) : "f"(hi), "f"(lo)); return d;
}

// ---------------- scratch (static device globals; no allocation) ----------------
__device__ float g_part[BB*NB*2];
__device__ float g_mv[4];
__device__ __nv_bfloat16 g_qkh[(size_t)BF*NN*E];   // [bf][n][e] unit-norm rows
__device__ __nv_bfloat16 g_vh [(size_t)BF*NN*C];   // [bf][c][n]
__device__ float g_y [(size_t)BB*CHW];
__device__ float g_h1[(size_t)BB*CHW];
__device__ float g_h2[(size_t)BB*CHW];

// ---------------- LayerNorm stats ----------------
__global__ void ln_partial_kernel(const float* __restrict__ x){
  int b = blockIdx.y;
  const float* xb = x + (size_t)b*CHW;
  float s = 0.f, ss = 0.f;
  for (int i = blockIdx.x*256 + threadIdx.x; i < CHW; i += NB*256){
    float v = xb[i]; s += v; ss += v*v;
  }
  #pragma unroll
  for (int o = 16; o; o >>= 1){
    s  += __shfl_xor_sync(0xffffffffu, s,  o);
    ss += __shfl_xor_sync(0xffffffffu, ss, o);
  }
  __shared__ float rs[8], rss[8];
  int warp = threadIdx.x >> 5, lane = threadIdx.x & 31;
  if (!lane){ rs[warp] = s; rss[warp] = ss; }
  __syncthreads();
  if (!threadIdx.x){
    float a = 0.f, c2 = 0.f;
    #pragma unroll
    for (int i = 0; i < 8; i++){ a += rs[i]; c2 += rss[i]; }
    g_part[(b*NB + blockIdx.x)*2]   = a;
    g_part[(b*NB + blockIdx.x)*2+1] = c2;
  }
}

__global__ void ln_final_kernel(){
  int b = blockIdx.x, t = threadIdx.x;
  float s  = g_part[(b*NB + t)*2];
  float ss = g_part[(b*NB + t)*2+1];
  #pragma unroll
  for (int o = 16; o; o >>= 1){
    s  += __shfl_xor_sync(0xffffffffu, s,  o);
    ss += __shfl_xor_sync(0xffffffffu, ss, o);
  }
  __shared__ float rs[8], rss[8];
  int warp = t >> 5, lane = t & 31;
  if (!lane){ rs[warp] = s; rss[warp] = ss; }
  __syncthreads();
  if (!t){
    float a = 0.f, c2 = 0.f;
    #pragma unroll
    for (int i = 0; i < 8; i++){ a += rs[i]; c2 += rss[i]; }
    float mean = a / (float)CHW;
    float var  = c2 / (float)CHW - mean*mean;
    g_mv[b*2]   = mean;
    g_mv[b*2+1] = rsqrtf(var + 1e-5f);
  }
}

// ---------------- prep: unshuffle + qk projection + row L2-norm ----------------
#define PREP_SMEM ((16384 + 8704 + 8448)*4)
__global__ __launch_bounds__(256) void prep_kernel(const float* __restrict__ x,
                                                   const float* __restrict__ wqk){
  int blk = blockIdx.x;
  int r0  = blk*64;
  int bf  = r0 / NN;
  int b   = bf >> 6, k = bf & 63, dy = k >> 3, dx = k & 7;
  float mean = g_mv[b*2], rstd = g_mv[b*2+1];
  extern __shared__ float sm[];
  float* ws = sm;                 // wqk [c][e]
  float* xt = sm + 16384;         // xn transposed [c][i], pitch 68
  float* qo = sm + 16384 + 8704;  // qk staging [i][e], pitch 132
  int tid = threadIdx.x;

  for (int l = tid; l < 16384; l += 256) ws[l] = wqk[l];

  int n0 = r0 - bf*NN;
  for (int l = tid; l < 8192; l += 256){
    int c = l >> 6, i = l & 63;
    int n  = n0 + i;
    int sh = n / SWID, swp = n - sh*SWID;
    int h  = sh*8 + dy, w = swp*8 + dx;
    float xv = x[(size_t)(b*C + c)*HW + h*W + w];
    g_vh[((size_t)bf*C + c)*NN + n] = __float2bfloat16(xv);
    xt[c*68 + i] = (xv - mean)*rstd;
  }
  __syncthreads();

  int tx = tid & 15, ty = tid >> 4;
  ull acc[4][4] = {};
  #pragma unroll 2
  for (int c = 0; c < 128; c++){
    float4 a = *(const float4*)&xt[c*68 + ty*4];
    const double2* wp = (const double2*)&ws[c*128 + tx*8];
    double2 wA = wp[0], wB = wp[1];
    ull w0 = d2u(wA.x), w1 = d2u(wA.y), w2 = d2u(wB.x), w3 = d2u(wB.y);
    ull a0 = pk2(a.x), a1 = pk2(a.y), a2 = pk2(a.z), a3 = pk2(a.w);
    ffma2(acc[0][0],a0,w0); ffma2(acc[0][1],a0,w1); ffma2(acc[0][2],a0,w2); ffma2(acc[0][3],a0,w3);
    ffma2(acc[1][0],a1,w0); ffma2(acc[1][1],a1,w1); ffma2(acc[1][2],a1,w2); ffma2(acc[1][3],a1,w3);
    ffma2(acc[2][0],a2,w0); ffma2(acc[2][1],a2,w1); ffma2(acc[2][2],a2,w2); ffma2(acc[2][3],a2,w3);
    ffma2(acc[3][0],a3,w0); ffma2(acc[3][1],a3,w1); ffma2(acc[3][2],a3,w2); ffma2(acc[3][3],a3,w3);
  }
  #pragma unroll
  for (int ii = 0; ii < 4; ii++){
    double2 s0 = make_double2(__longlong_as_double(acc[ii][0]), __longlong_as_double(acc[ii][1]));
    double2 s1 = make_double2(__longlong_as_double(acc[ii][2]), __longlong_as_double(acc[ii][3]));
    *(double2*)&qo[(ty*4+ii)*132 + tx*8]     = s0;
    *(double2*)&qo[(ty*4+ii)*132 + tx*8 + 4] = s1;
  }
  __syncthreads();

  int r = tid >> 2, q = tid & 3;
  float ssq = 0.f;
  for (int j = q; j < 128; j += 4){ float v = qo[r*132 + j]; ssq += v*v; }
  ssq += __shfl_xor_sync(0xffffffffu, ssq, 1);
  ssq += __shfl_xor_sync(0xffffffffu, ssq, 2);
  float inv = 1.f/(sqrtf(ssq) + 1e-8f);
  for (int j = q; j < 128; j += 4)
    g_qkh[(size_t)(r0 + r)*E + j] = __float2bfloat16(qo[r*132 + j]*inv);
}

// ---------------- attention: mma.sync bf16 flash, no-max softmax ----------------
// smem: Q 16K | K0 16K | K1 16K | V0 16K | V1 16K  = 80K
#define AOFF_Q  0
#define AOFF_K0 16384
#define AOFF_K1 32768
#define AOFF_V0 49152
#define AOFF_V1 65536
#define ATTN_SMEM 81920

__device__ __forceinline__ void load_kv(uint32_t sb, const __nv_bfloat16* qsrc,
                                        const __nv_bfloat16* vsrc, int jt, int tid){
  uint32_t kb = sb + ((jt & 1) ? AOFF_K1 : AOFF_K0);
  uint32_t vb = sb + ((jt & 1) ? AOFF_V1 : AOFF_V0);
  const __nv_bfloat16* ks = qsrc + (size_t)jt*64*E;
  #pragma unroll
  for (int r = 0; r < 8; r++){
    int idx = tid + 128*r;
    int row = idx >> 4, ch = idx & 15;
    cp16(kb + row*256 + ((ch ^ (row & 7))*16), ks + (size_t)row*E + ch*8);
  }
  const __nv_bfloat16* vs = vsrc + jt*64;
  #pragma unroll
  for (int r = 0; r < 8; r++){
    int idx = tid + 128*r;
    int row = idx >> 3, ch = idx & 7;
    cp16(vb + row*128 + ((ch ^ (row & 7))*16), vs + (size_t)row*NN + ch*8);
  }
  CP_COMMIT();
}

__global__ __launch_bounds__(128) void attn_mma_kernel(const float* __restrict__ x){
  extern __shared__ char smc[];
  const int tid = threadIdx.x;
  const int lane = tid & 31, w = tid >> 5;
  const int rt = blockIdx.x, bf = blockIdx.y;
  const int r0 = rt*64;
  const __nv_bfloat16* qsrc = g_qkh + (size_t)bf*NN*E;
  const __nv_bfloat16* vsrc = g_vh  + (size_t)bf*C*NN;
  uint32_t sb = s2u(smc);

  { // Q tile -> smem
    const __nv_bfloat16* qs = qsrc + (size_t)r0*E;
    #pragma unroll
    for (int r = 0; r < 8; r++){
      int idx = tid + 128*r;
      int row = idx >> 4, ch = idx & 15;
      cp16(sb + AOFF_Q + row*256 + ((ch ^ (row & 7))*16), qs + (size_t)row*E + ch*8);
    }
    CP_COMMIT();
  }
  load_kv(sb, qsrc, vsrc, 0, tid);
  asm volatile("cp.async.wait_group 1;" ::: "memory");
  __syncthreads();

  // preload Q A-fragments (stay in regs whole kernel)
  uint32_t qa[8][4];
  #pragma unroll
  for (int kk = 0; kk < 8; kk++){
    int row = w*16 + (lane & 15);
    int ch  = kk*2 + (lane >> 4);
    ldsm4(qa[kk], sb + AOFF_Q + row*256 + ((ch ^ (row & 7))*16));
  }

  float oacc[16][4];
  #pragma unroll
  for (int i = 0; i < 16; i++){ oacc[i][0]=0.f; oacc[i][1]=0.f; oacc[i][2]=0.f; oacc[i][3]=0.f; }
  float rsum0 = 0.f, rsum1 = 0.f;
  const float invsE = 0.08838834764831845f;   // 1/sqrt(128); (s+1) shift cancels in softmax

  for (int jt = 0; jt < 9; jt++){
    __syncthreads();
    if (jt < 8){
      load_kv(sb, qsrc, vsrc, jt+1, tid);
      asm volatile("cp.async.wait_group 1;" ::: "memory");
    } else {
      asm volatile("cp.async.wait_group 0;" ::: "memory");
    }
    __syncthreads();

    uint32_t kbase = sb + ((jt & 1) ? AOFF_K1 : AOFF_K0);
    uint32_t vbase = sb + ((jt & 1) ? AOFF_V1 : AOFF_V0);

    // S = Q K^T : per warp 16x64
    float sc[8][4];
    #pragma unroll
    for (int i = 0; i < 8; i++){ sc[i][0]=0.f; sc[i][1]=0.f; sc[i][2]=0.f; sc[i][3]=0.f; }
    #pragma unroll
    for (int jp = 0; jp < 4; jp++){
      #pragma unroll
      for (int kk = 0; kk < 8; kk++){
        uint32_t kb[4];
        int row = jp*16 + (lane & 15);
        int ch  = kk*2 + (lane >> 4);
        ldsm4(kb, kbase + row*256 + ((ch ^ (row & 7))*16));
        mma_bf16(sc[2*jp],   qa[kk], kb[0], kb[2]);
        mma_bf16(sc[2*jp+1], qa[kk], kb[1], kb[3]);
      }
    }

    // exp + repack C-frags (f32) into A-frags (bf16) — no smem round-trip
    uint32_t pa[4][4];
    #pragma unroll
    for (int j = 0; j < 8; j++){
      float p0 = __expf(sc[j][0]*invsE), p1 = __expf(sc[j][1]*invsE);
      float p2 = __expf(sc[j][2]*invsE), p3 = __expf(sc[j][3]*invsE);
      rsum0 += p0 + p1; rsum1 += p2 + p3;
      int kk = j >> 1;
      if ((j & 1) == 0){ pa[kk][0] = packbf(p0,p1); pa[kk][1] = packbf(p2,p3); }
      else             { pa[kk][2] = packbf(p0,p1); pa[kk][3] = packbf(p2,p3); }
    }

    // O += P V : per warp 16x128
    #pragma unroll
    for (int jnp = 0; jnp < 8; jnp++){
      #pragma unroll
      for (int kk = 0; kk < 4; kk++){
        uint32_t vb[4];
        int row = jnp*16 + (lane & 15);
        int ch  = kk*2 + (lane >> 4);
        ldsm4(vb, vbase + row*128 + ((ch ^ (row & 7))*16));
        mma_bf16(oacc[2*jnp],   pa[kk], vb[0], vb[2]);
        mma_bf16(oacc[2*jnp+1], pa[kk], vb[1], vb[3]);
      }
    }
  }

  // row-sum reduce across the 4 lanes of each row group
  rsum0 += __shfl_xor_sync(0xffffffffu, rsum0, 1);
  rsum0 += __shfl_xor_sync(0xffffffffu, rsum0, 2);
  rsum1 += __shfl_xor_sync(0xffffffffu, rsum1, 1);
  rsum1 += __shfl_xor_sync(0xffffffffu, rsum1, 2);
  float inv0 = 1.f/rsum0, inv1 = 1.f/rsum1;

  // residual + shuffle back to [B,C,H,W]
  int g = lane >> 2, t4 = lane & 3;
  int b = bf >> 6, kk2 = bf & 63, dy = kk2 >> 3, dx = kk2 & 7;
  int nA = r0 + w*16 + g;
  int nB = nA + 8;
  int shA = nA / SWID, swA = nA - shA*SWID;
  int shB = nB / SWID, swB = nB - shB*SWID;
  size_t baseA = (size_t)b*CHW + (size_t)(shA*8 + dy)*W + (swA*8 + dx);
  size_t baseB = (size_t)b*CHW + (size_t)(shB*8 + dy)*W + (swB*8 + dx);
  #pragma unroll
  for (int jn = 0; jn < 16; jn++){
    int c0 = jn*8 + 2*t4;
    size_t giA = baseA + (size_t)c0*HW;
    size_t giB = baseB + (size_t)c0*HW;
    g_y[giA]    = x[giA]    + oacc[jn][0]*inv0;
    g_y[giA+HW] = x[giA+HW] + oacc[jn][1]*inv0;
    g_y[giB]    = x[giB]    + oacc[jn][2]*inv1;
    g_y[giB+HW] = x[giB+HW] + oacc[jn][3]*inv1;
  }
}

// ---------------- 3x3 dilated conv (dil=2, pad=2) + ReLU ----------------
#define CONV_SMEM ((12800 + 10368)*4)
__global__ __launch_bounds__(256,2) void conv3x3_kernel(const float* __restrict__ in,
                                                        const float* __restrict__ wt,
                                                        const float* __restrict__ bias,
                                                        float* __restrict__ out){
  int txle = blockIdx.x*16, tyle = blockIdx.y*16;
  int z = blockIdx.z; int b = z >> 2; int cog = z & 3;
  extern __shared__ float sm[];
  float* ins = sm;            // [ci][yy][xx], 32*400
  float* ws  = sm + 12800;    // [ci*9+kk][co], pitch 36
  int tid = threadIdx.x;
  int cog_t = tid >> 6;
  int pxg   = tid & 63;
  int x0 = (pxg & 3)*4, y0 = pxg >> 2;
  ull acc[4][4] = {};

  for (int ch = 0; ch < 4; ch++){
    __syncthreads();
    for (int l = tid; l < 12800; l += 256){
      int ci = l / 400, r = l - ci*400, yy = r / 20, xx = r - yy*20;
      int gy = tyle - 2 + yy, gx = txle - 2 + xx;
      float v = 0.f;
      if (gy >= 0 && gy < H && gx >= 0 && gx < W)
        v = in[(size_t)(b*C + ch*32 + ci)*HW + gy*W + gx];
      ins[l] = v;
    }
    for (int l = tid; l < 9216; l += 256){
      int co_l = l / 288, r = l - co_l*288;
      ws[r*36 + co_l] = wt[(size_t)(cog*32 + co_l)*(C*9) + ch*288 + r];
    }
    __syncthreads();
    for (int ci = 0; ci < 32; ci++){
      const float* ip   = &ins[ci*400 + y0*20 + x0];
      const float* wrow = &ws[(ci*9)*36 + cog_t*8];
      #pragma unroll
      for (int ky = 0; ky < 3; ky++){
        float4 ra = *(const float4*)(ip + ky*40);
        float4 rb = *(const float4*)(ip + ky*40 + 4);
        ull bc[8] = {pk2(ra.x),pk2(ra.y),pk2(ra.z),pk2(ra.w),
                     pk2(rb.x),pk2(rb.y),pk2(rb.z),pk2(rb.w)};
        #pragma unroll
        for (int kx = 0; kx < 3; kx++){
          const double2* wp = (const double2*)(wrow + (ky*3+kx)*36);
          double2 wA = wp[0], wB = wp[1];
          ull w0 = d2u(wA.x), w1 = d2u(wA.y), w2 = d2u(wB.x), w3 = d2u(wB.y);
          #pragma unroll
          for (int p = 0; p < 4; p++){
            ull bv = bc[p + 2*kx];
            ffma2(acc[0][p], bv, w0);
            ffma2(acc[1][p], bv, w1);
            ffma2(acc[2][p], bv, w2);
            ffma2(acc[3][p], bv, w3);
          }
        }
      }
    }
  }

  int gy = tyle + y0, gx = txle + x0;
  #pragma unroll
  for (int cp = 0; cp < 4; cp++){
    float2 o0 = upk(acc[cp][0]), o1 = upk(acc[cp][1]);
    float2 o2 = upk(acc[cp][2]), o3 = upk(acc[cp][3]);
    int coA = cog*32 + cog_t*8 + 2*cp;
    float bA = bias[coA], bB = bias[coA+1];
    float4 qa = make_float4(fmaxf(o0.x+bA,0.f), fmaxf(o1.x+bA,0.f),
                            fmaxf(o2.x+bA,0.f), fmaxf(o3.x+bA,0.f));
    float4 qb = make_float4(fmaxf(o0.y+bB,0.f), fmaxf(o1.y+bB,0.f),
                            fmaxf(o2.y+bB,0.f), fmaxf(o3.y+bB,0.f));
    *(float4*)&out[(size_t)(b*C + coA  )*HW + (size_t)gy*W + gx] = qa;
    *(float4*)&out[(size_t)(b*C + coA+1)*HW + (size_t)gy*W + gx] = qb;
  }
}

// ---------------- 1x1 conv + bias + residual ----------------
#define C1_SMEM ((16896 + 8704)*4)
__global__ __launch_bounds__(256) void conv1x1_res_kernel(const float* __restrict__ hin,
                                                          const float* __restrict__ w3,
                                                          const float* __restrict__ b3,
                                                          const float* __restrict__ x,
                                                          float* __restrict__ out){
  int blk = blockIdx.x;
  int b   = blk / (HW/64);
  int hw0 = (blk - b*(HW/64))*64;
  extern __shared__ float sm[];
  float* w3t = sm;            // [ci][co], pitch 132
  float* hs  = sm + 16896;    // [ci][px], pitch 68
  int tid = threadIdx.x;
  for (int l = tid; l < 16384; l += 256){
    int co = l >> 7, ci = l & 127;
    w3t[ci*132 + co] = w3[l];
  }
  for (int l = tid; l < 8192; l += 256){
    int ci = l >> 6, p = l & 63;
    hs[ci*68 + p] = hin[(size_t)(b*C + ci)*HW + hw0 + p];
  }
  __syncthreads();

  int tx = tid & 15, ty = tid >> 4;
  ull acc[4][4] = {};
  #pragma unroll 2
  for (int ci = 0; ci < 128; ci++){
    float4 a = *(const float4*)&hs[ci*68 + tx*4];
    const double2* wp = (const double2*)&w3t[ci*132 + ty*8];
    double2 wA = wp[0], wB = wp[1];
    ull w0 = d2u(wA.x), w1 = d2u(wA.y), w2 = d2u(wB.x), w3v = d2u(wB.y);
    ull a0 = pk2(a.x), a1 = pk2(a.y), a2 = pk2(a.z), a3 = pk2(a.w);
    ffma2(acc[0][0],a0,w0); ffma2(acc[0][1],a0,w1); ffma2(acc[0][2],a0,w2); ffma2(acc[0][3],a0,w3v);
    ffma2(acc[1][0],a1,w0); ffma2(acc[1][1],a1,w1); ffma2(acc[1][2],a1,w2); ffma2(acc[1][3],a1,w3v);
    ffma2(acc[2][0],a2,w0); ffma2(acc[2][1],a2,w1); ffma2(acc[2][2],a2,w2); ffma2(acc[2][3],a2,w3v);
    ffma2(acc[3][0],a3,w0); ffma2(acc[3][1],a3,w1); ffma2(acc[3][2],a3,w2); ffma2(acc[3][3],a3,w3v);
  }
  #pragma unroll
  for (int cp = 0; cp < 4; cp++){
    float2 u0 = upk(acc[0][cp]), u1 = upk(acc[1][cp]);
    float2 u2 = upk(acc[2][cp]), u3 = upk(acc[3][cp]);
    int coA = ty*8 + 2*cp;
    float bA = b3[coA], bB = b3[coA+1];
    size_t giA = (size_t)(b*C + coA)*HW + hw0 + tx*4;
    size_t giB = giA + HW;
    float4 xa = *(const float4*)&x[giA];
    float4 xb = *(const float4*)&x[giB];
    *(float4*)&out[giA] = make_float4(xa.x+u0.x+bA, xa.y+u1.x+bA, xa.z+u2.x+bA, xa.w+u3.x+bA);
    *(float4*)&out[giB] = make_float4(xb.x+u0.y+bB, xb.y+u1.y+bB, xb.z+u2.y+bB, xb.w+u3.y+bB);
  }
}

// ---------------- launch ----------------
extern "C" void kernel_launch(void* const* d_in, const int* in_sizes, int n_in,
                              void* d_out, int out_size){
  const float* x   = (const float*)d_in[0];
  const float* wqk = (const float*)d_in[1];
  const float* w1  = (const float*)d_in[2];
  const float* b1  = (const float*)d_in[3];
  const float* w2  = (const float*)d_in[4];
  const float* b2  = (const float*)d_in[5];
  const float* w3  = (const float*)d_in[6];
  const float* b3  = (const float*)d_in[7];
  float* out = (float*)d_out;

  cudaFuncSetAttribute(prep_kernel,        cudaFuncAttributeMaxDynamicSharedMemorySize, PREP_SMEM);
  cudaFuncSetAttribute(attn_mma_kernel,    cudaFuncAttributeMaxDynamicSharedMemorySize, ATTN_SMEM);
  cudaFuncSetAttribute(conv3x3_kernel,     cudaFuncAttributeMaxDynamicSharedMemorySize, CONV_SMEM);
  cudaFuncSetAttribute(conv1x1_res_kernel, cudaFuncAttributeMaxDynamicSharedMemorySize, C1_SMEM);

  void *py_, *ph1_, *ph2_;
  cudaGetSymbolAddress(&py_,  g_y);
  cudaGetSymbolAddress(&ph1_, g_h1);
  cudaGetSymbolAddress(&ph2_, g_h2);
  float* py  = (float*)py_;
  float* ph1 = (float*)ph1_;
  float* ph2 = (float*)ph2_;

  ln_partial_kernel<<<dim3(NB, BB), 256>>>(x);
  ln_final_kernel<<<BB, 256>>>();
  prep_kernel<<<(BF*NN)/64, 256, PREP_SMEM>>>(x, wqk);
  attn_mma_kernel<<<dim3(9, BF), 128, ATTN_SMEM>>>(x);
  conv3x3_kernel<<<dim3(12,12,8), 256, CONV_SMEM>>>(py,  w1, b1, ph1);
  conv3x3_kernel<<<dim3(12,12,8), 256, CONV_SMEM>>>(ph1, w2, b2, ph2);
  conv1x1_res_kernel<<<(BB*HW)/64, 256, C1_SMEM>>>(ph2, w3, b3, x, out);
}

// round 6
// speedup vs baseline: 3.6781x; 1.9222x over previous
#include <cuda_runtime.h>
#include <cuda_bf16.h>
#include <math.h>
#include <stdint.h>

#define BB 2
#define C 128
#define H 192
#define W 192
#define HW (H*W)
#define CHW (C*HW)
#define E 128
#define SWID 24
#define NN 576
#define BF 128
#define NB 256

typedef unsigned long long ull;

// ---------------- packed f32x2 helpers (prep kernel) ----------------
__device__ __forceinline__ ull pk2(float v){
  ull r; asm("mov.b64 %0, {%1, %1};" : "=l"(r) : "f"(v)); return r;
}
__device__ __forceinline__ void ffma2(ull &d, ull a, ull b){
  asm("fma.rn.f32x2 %0, %1, %2, %3;" : "=l"(d) : "l"(a), "l"(b), "l"(d));
}
__device__ __forceinline__ ull d2u(double d){ return __double_as_longlong(d); }

// ---------------- mma helpers (base PTX, compute_103-safe) ----------------
__device__ __forceinline__ uint32_t s2u(const void* p){
  uint32_t a;
  asm("{ .reg .u64 t; cvta.to.shared.u64 t, %1; cvt.u32.u64 %0, t; }" : "=r"(a) : "l"(p));
  return a;
}
__device__ __forceinline__ void cp16(uint32_t d, const void* g){
  asm volatile("cp.async.cg.shared.global [%0], [%1], 16;" :: "r"(d), "l"(g));
}
#define CP_COMMIT() asm volatile("cp.async.commit_group;" ::: "memory")

__device__ __forceinline__ void ldsm4(uint32_t* r, uint32_t addr){
  asm volatile("ldmatrix.sync.aligned.m8n8.x4.shared.b16 {%0,%1,%2,%3}, [%4];"
    : "=r"(r[0]),"=r"(r[1]),"=r"(r[2]),"=r"(r[3]) : "r"(addr));
}
__device__ __forceinline__ void mma_bf16(float* c, const uint32_t* a, uint32_t b0, uint32_t b1){
  asm volatile("mma.sync.aligned.m16n8k16.row.col.f32.bf16.bf16.f32 "
    "{%0,%1,%2,%3}, {%4,%5,%6,%7}, {%8,%9}, {%0,%1,%2,%3};"
    : "+f"(c[0]),"+f"(c[1]),"+f"(c[2]),"+f"(c[3])
    : "r"(a[0]),"r"(a[1]),"r"(a[2]),"r"(a[3]), "r"(b0),"r"(b1));
}
__device__ __forceinline__ void mma_tf32(float* c, uint32_t a0, uint32_t a1, uint32_t a2,
                                         uint32_t a3, uint32_t b0, uint32_t b1){
  asm volatile("mma.sync.aligned.m16n8k8.row.col.f32.tf32.tf32.f32 "
    "{%0,%1,%2,%3}, {%4,%5,%6,%7}, {%8,%9}, {%0,%1,%2,%3};"
    : "+f"(c[0]),"+f"(c[1]),"+f"(c[2]),"+f"(c[3])
    : "r"(a0),"r"(a1),"r"(a2),"r"(a3), "r"(b0),"r"(b1));
}
__device__ __forceinline__ uint32_t packbf(float lo, float hi){
  uint32_t d; asm("cvt.rn.bf16x2.f32 %0, %1, %2;" : "=r"(d) : "f"(hi), "f"(lo)); return d;
}
__device__ __forceinline__ float tf32r(float v){
  uint32_t o; asm("cvt.rna.tf32.f32 %0, %1;" : "=r"(o) : "f"(v));
  return __uint_as_float(o);
}
__device__ __forceinline__ uint32_t ldss(uint32_t a){
  uint32_t v; asm volatile("ld.shared.b32 %0, [%1];" : "=r"(v) : "r"(a)); return v;
}

// ---------------- scratch (static device globals; no allocation) ----------------
__device__ float g_part[BB*NB*2];
__device__ float g_mv[4];
__device__ __nv_bfloat16 g_qkh[(size_t)BF*NN*E];   // [bf][n][e] unit-norm rows
__device__ __nv_bfloat16 g_vh [(size_t)BF*NN*C];   // [bf][c][n]
__device__ float g_y [(size_t)BB*CHW];
__device__ float g_h1[(size_t)BB*CHW];
__device__ float g_h2[(size_t)BB*CHW];
__device__ float2 g_wp1[73728];   // [kk][ci8][n8][lane] pre-rounded fragment pairs
__device__ float2 g_wp2[73728];
__device__ float2 g_wp3[8192];    // [ci8][n8][lane]

// ---------------- LayerNorm stats ----------------
__global__ void ln_partial_kernel(const float* __restrict__ x){
  int b = blockIdx.y;
  const float* xb = x + (size_t)b*CHW;
  float s = 0.f, ss = 0.f;
  for (int i = blockIdx.x*256 + threadIdx.x; i < CHW; i += NB*256){
    float v = xb[i]; s += v; ss += v*v;
  }
  #pragma unroll
  for (int o = 16; o; o >>= 1){
    s  += __shfl_xor_sync(0xffffffffu, s,  o);
    ss += __shfl_xor_sync(0xffffffffu, ss, o);
  }
  __shared__ float rs[8], rss[8];
  int warp = threadIdx.x >> 5, lane = threadIdx.x & 31;
  if (!lane){ rs[warp] = s; rss[warp] = ss; }
  __syncthreads();
  if (!threadIdx.x){
    float a = 0.f, c2 = 0.f;
    #pragma unroll
    for (int i = 0; i < 8; i++){ a += rs[i]; c2 += rss[i]; }
    g_part[(b*NB + blockIdx.x)*2]   = a;
    g_part[(b*NB + blockIdx.x)*2+1] = c2;
  }
}

__global__ void ln_final_kernel(){
  int b = blockIdx.x, t = threadIdx.x;
  float s  = g_part[(b*NB + t)*2];
  float ss = g_part[(b*NB + t)*2+1];
  #pragma unroll
  for (int o = 16; o; o >>= 1){
    s  += __shfl_xor_sync(0xffffffffu, s,  o);
    ss += __shfl_xor_sync(0xffffffffu, ss, o);
  }
  __shared__ float rs[8], rss[8];
  int warp = t >> 5, lane = t & 31;
  if (!lane){ rs[warp] = s; rss[warp] = ss; }
  __syncthreads();
  if (!t){
    float a = 0.f, c2 = 0.f;
    #pragma unroll
    for (int i = 0; i < 8; i++){ a += rs[i]; c2 += rss[i]; }
    float mean = a / (float)CHW;
    float var  = c2 / (float)CHW - mean*mean;
    g_mv[b*2]   = mean;
    g_mv[b*2+1] = rsqrtf(var + 1e-5f);
  }
}

// ---------------- weight prepack: fragment-order, tf32-rounded ----------------
__global__ void prepack_kernel(const float* __restrict__ w1, const float* __restrict__ w2,
                               const float* __restrict__ w3){
  int i = blockIdx.x*256 + threadIdx.x;
  if (i < 2*73728){
    const float* w = (i < 73728) ? w1 : w2;
    float2* dst = (i < 73728) ? g_wp1 : g_wp2;
    int j = (i < 73728) ? i : i - 73728;
    int lane = j & 31, n8 = (j >> 5) & 15, ci8 = (j >> 9) & 15, kk = j >> 13;
    int t = lane & 3, g = lane >> 2;
    int co = n8*8 + g, ci = ci8*8 + t;
    float b0 = w[(co*128 + ci)*9 + kk];
    float b1 = w[(co*128 + ci + 4)*9 + kk];
    dst[j] = make_float2(tf32r(b0), tf32r(b1));
  } else {
    int j = i - 2*73728;
    if (j < 8192){
      int lane = j & 31, n8 = (j >> 5) & 15, ci8 = j >> 9;
      int t = lane & 3, g = lane >> 2;
      float b0 = w3[(n8*8 + g)*128 + ci8*8 + t];
      float b1 = w3[(n8*8 + g)*128 + ci8*8 + t + 4];
      g_wp3[j] = make_float2(tf32r(b0), tf32r(b1));
    }
  }
}

// ---------------- prep: unshuffle + qk projection + row L2-norm ----------------
#define PREP_SMEM ((16384 + 8704 + 8448)*4)
__global__ __launch_bounds__(256) void prep_kernel(const float* __restrict__ x,
                                                   const float* __restrict__ wqk){
  int blk = blockIdx.x;
  int r0  = blk*64;
  int bf  = r0 / NN;
  int b   = bf >> 6, k = bf & 63, dy = k >> 3, dx = k & 7;
  float mean = g_mv[b*2], rstd = g_mv[b*2+1];
  extern __shared__ float sm[];
  float* ws = sm;
  float* xt = sm + 16384;
  float* qo = sm + 16384 + 8704;
  int tid = threadIdx.x;

  for (int l = tid; l < 16384; l += 256) ws[l] = wqk[l];

  int n0 = r0 - bf*NN;
  for (int l = tid; l < 8192; l += 256){
    int c = l >> 6, i = l & 63;
    int n  = n0 + i;
    int sh = n / SWID, swp = n - sh*SWID;
    int h  = sh*8 + dy, w = swp*8 + dx;
    float xv = x[(size_t)(b*C + c)*HW + h*W + w];
    g_vh[((size_t)bf*C + c)*NN + n] = __float2bfloat16(xv);
    xt[c*68 + i] = (xv - mean)*rstd;
  }
  __syncthreads();

  int tx = tid & 15, ty = tid >> 4;
  ull acc[4][4] = {};
  #pragma unroll 2
  for (int c = 0; c < 128; c++){
    float4 a = *(const float4*)&xt[c*68 + ty*4];
    const double2* wp = (const double2*)&ws[c*128 + tx*8];
    double2 wA = wp[0], wB = wp[1];
    ull w0 = d2u(wA.x), w1 = d2u(wA.y), w2 = d2u(wB.x), w3 = d2u(wB.y);
    ull a0 = pk2(a.x), a1 = pk2(a.y), a2 = pk2(a.z), a3 = pk2(a.w);
    ffma2(acc[0][0],a0,w0); ffma2(acc[0][1],a0,w1); ffma2(acc[0][2],a0,w2); ffma2(acc[0][3],a0,w3);
    ffma2(acc[1][0],a1,w0); ffma2(acc[1][1],a1,w1); ffma2(acc[1][2],a1,w2); ffma2(acc[1][3],a1,w3);
    ffma2(acc[2][0],a2,w0); ffma2(acc[2][1],a2,w1); ffma2(acc[2][2],a2,w2); ffma2(acc[2][3],a2,w3);
    ffma2(acc[3][0],a3,w0); ffma2(acc[3][1],a3,w1); ffma2(acc[3][2],a3,w2); ffma2(acc[3][3],a3,w3);
  }
  #pragma unroll
  for (int ii = 0; ii < 4; ii++){
    double2 s0 = make_double2(__longlong_as_double(acc[ii][0]), __longlong_as_double(acc[ii][1]));
    double2 s1 = make_double2(__longlong_as_double(acc[ii][2]), __longlong_as_double(acc[ii][3]));
    *(double2*)&qo[(ty*4+ii)*132 + tx*8]     = s0;
    *(double2*)&qo[(ty*4+ii)*132 + tx*8 + 4] = s1;
  }
  __syncthreads();

  int r = tid >> 2, q = tid & 3;
  float ssq = 0.f;
  for (int j = q; j < 128; j += 4){ float v = qo[r*132 + j]; ssq += v*v; }
  ssq += __shfl_xor_sync(0xffffffffu, ssq, 1);
  ssq += __shfl_xor_sync(0xffffffffu, ssq, 2);
  float inv = 1.f/(sqrtf(ssq) + 1e-8f);
  for (int j = q; j < 128; j += 4)
    g_qkh[(size_t)(r0 + r)*E + j] = __float2bfloat16(qo[r*132 + j]*inv);
}

// ---------------- attention: mma.sync bf16 flash, no-max softmax ----------------
#define AOFF_Q  0
#define AOFF_K0 16384
#define AOFF_K1 32768
#define AOFF_V0 49152
#define AOFF_V1 65536
#define ATTN_SMEM 81920

__device__ __forceinline__ void load_kv(uint32_t sb, const __nv_bfloat16* qsrc,
                                        const __nv_bfloat16* vsrc, int jt, int tid){
  uint32_t kb = sb + ((jt & 1) ? AOFF_K1 : AOFF_K0);
  uint32_t vb = sb + ((jt & 1) ? AOFF_V1 : AOFF_V0);
  const __nv_bfloat16* ks = qsrc + (size_t)jt*64*E;
  #pragma unroll
  for (int r = 0; r < 8; r++){
    int idx = tid + 128*r;
    int row = idx >> 4, ch = idx & 15;
    cp16(kb + row*256 + ((ch ^ (row & 7))*16), ks + (size_t)row*E + ch*8);
  }
  const __nv_bfloat16* vs = vsrc + jt*64;
  #pragma unroll
  for (int r = 0; r < 8; r++){
    int idx = tid + 128*r;
    int row = idx >> 3, ch = idx & 7;
    cp16(vb + row*128 + ((ch ^ (row & 7))*16), vs + (size_t)row*NN + ch*8);
  }
  CP_COMMIT();
}

__global__ __launch_bounds__(128) void attn_mma_kernel(const float* __restrict__ x){
  extern __shared__ char smc[];
  const int tid = threadIdx.x;
  const int lane = tid & 31, w = tid >> 5;
  const int rt = blockIdx.x, bf = blockIdx.y;
  const int r0 = rt*64;
  const __nv_bfloat16* qsrc = g_qkh + (size_t)bf*NN*E;
  const __nv_bfloat16* vsrc = g_vh  + (size_t)bf*C*NN;
  uint32_t sb = s2u(smc);

  {
    const __nv_bfloat16* qs = qsrc + (size_t)r0*E;
    #pragma unroll
    for (int r = 0; r < 8; r++){
      int idx = tid + 128*r;
      int row = idx >> 4, ch = idx & 15;
      cp16(sb + AOFF_Q + row*256 + ((ch ^ (row & 7))*16), qs + (size_t)row*E + ch*8);
    }
    CP_COMMIT();
  }
  load_kv(sb, qsrc, vsrc, 0, tid);
  asm volatile("cp.async.wait_group 1;" ::: "memory");
  __syncthreads();

  uint32_t qa[8][4];
  #pragma unroll
  for (int kk = 0; kk < 8; kk++){
    int row = w*16 + (lane & 15);
    int ch  = kk*2 + (lane >> 4);
    ldsm4(qa[kk], sb + AOFF_Q + row*256 + ((ch ^ (row & 7))*16));
  }

  float oacc[16][4];
  #pragma unroll
  for (int i = 0; i < 16; i++){ oacc[i][0]=0.f; oacc[i][1]=0.f; oacc[i][2]=0.f; oacc[i][3]=0.f; }
  float rsum0 = 0.f, rsum1 = 0.f;
  const float invsE = 0.08838834764831845f;

  for (int jt = 0; jt < 9; jt++){
    __syncthreads();
    if (jt < 8){
      load_kv(sb, qsrc, vsrc, jt+1, tid);
      asm volatile("cp.async.wait_group 1;" ::: "memory");
    } else {
      asm volatile("cp.async.wait_group 0;" ::: "memory");
    }
    __syncthreads();

    uint32_t kbase = sb + ((jt & 1) ? AOFF_K1 : AOFF_K0);
    uint32_t vbase = sb + ((jt & 1) ? AOFF_V1 : AOFF_V0);

    float sc[8][4];
    #pragma unroll
    for (int i = 0; i < 8; i++){ sc[i][0]=0.f; sc[i][1]=0.f; sc[i][2]=0.f; sc[i][3]=0.f; }
    #pragma unroll
    for (int jp = 0; jp < 4; jp++){
      #pragma unroll
      for (int kk = 0; kk < 8; kk++){
        uint32_t kb[4];
        int row = jp*16 + (lane & 15);
        int ch  = kk*2 + (lane >> 4);
        ldsm4(kb, kbase + row*256 + ((ch ^ (row & 7))*16));
        mma_bf16(sc[2*jp],   qa[kk], kb[0], kb[2]);
        mma_bf16(sc[2*jp+1], qa[kk], kb[1], kb[3]);
      }
    }

    uint32_t pa[4][4];
    #pragma unroll
    for (int j = 0; j < 8; j++){
      float p0 = __expf(sc[j][0]*invsE), p1 = __expf(sc[j][1]*invsE);
      float p2 = __expf(sc[j][2]*invsE), p3 = __expf(sc[j][3]*invsE);
      rsum0 += p0 + p1; rsum1 += p2 + p3;
      int kk = j >> 1;
      if ((j & 1) == 0){ pa[kk][0] = packbf(p0,p1); pa[kk][1] = packbf(p2,p3); }
      else             { pa[kk][2] = packbf(p0,p1); pa[kk][3] = packbf(p2,p3); }
    }

    #pragma unroll
    for (int jnp = 0; jnp < 8; jnp++){
      #pragma unroll
      for (int kk = 0; kk < 4; kk++){
        uint32_t vb[4];
        int row = jnp*16 + (lane & 15);
        int ch  = kk*2 + (lane >> 4);
        ldsm4(vb, vbase + row*128 + ((ch ^ (row & 7))*16));
        mma_bf16(oacc[2*jnp],   pa[kk], vb[0], vb[2]);
        mma_bf16(oacc[2*jnp+1], pa[kk], vb[1], vb[3]);
      }
    }
  }

  rsum0 += __shfl_xor_sync(0xffffffffu, rsum0, 1);
  rsum0 += __shfl_xor_sync(0xffffffffu, rsum0, 2);
  rsum1 += __shfl_xor_sync(0xffffffffu, rsum1, 1);
  rsum1 += __shfl_xor_sync(0xffffffffu, rsum1, 2);
  float inv0 = 1.f/rsum0, inv1 = 1.f/rsum1;

  int g = lane >> 2, t4 = lane & 3;
  int b = bf >> 6, kk2 = bf & 63, dy = kk2 >> 3, dx = kk2 & 7;
  int nA = r0 + w*16 + g;
  int nB = nA + 8;
  int shA = nA / SWID, swA = nA - shA*SWID;
  int shB = nB / SWID, swB = nB - shB*SWID;
  size_t baseA = (size_t)b*CHW + (size_t)(shA*8 + dy)*W + (swA*8 + dx);
  size_t baseB = (size_t)b*CHW + (size_t)(shB*8 + dy)*W + (swB*8 + dx);
  #pragma unroll
  for (int jn = 0; jn < 16; jn++){
    int c0 = jn*8 + 2*t4;
    size_t giA = baseA + (size_t)c0*HW;
    size_t giB = baseB + (size_t)c0*HW;
    g_y[giA]    = x[giA]    + oacc[jn][0]*inv0;
    g_y[giA+HW] = x[giA+HW] + oacc[jn][1]*inv0;
    g_y[giB]    = x[giB]    + oacc[jn][2]*inv1;
    g_y[giB+HW] = x[giB+HW] + oacc[jn][3]*inv1;
  }
}

// ---------------- 3x3 dilated conv via tf32 mma implicit GEMM ----------------
// block: 256 thr (8 warps), tile 16x(x) * 8y pixels, all 128 co. smem: ins [32ci][248]
#define C3_SMEM (7936*4)
__global__ __launch_bounds__(256) void conv3_mma_kernel(const float* __restrict__ in,
                                                        const float2* __restrict__ wp,
                                                        const float* __restrict__ bias,
                                                        float* __restrict__ out){
  int txle = blockIdx.x*16, tyle = blockIdx.y*8, b = blockIdx.z;
  extern __shared__ float sm[];
  int tid = threadIdx.x, lane = tid & 31, wm = tid >> 5;
  int t = lane & 3, g = lane >> 2;
  uint32_t sb = s2u(sm);
  float acc[16][4] = {};

  for (int chunk = 0; chunk < 4; chunk++){
    __syncthreads();
    for (int l = tid; l < 7680; l += 256){
      int ci = l / 240, r = l - ci*240, yy = r / 20, xx = r - yy*20;
      int gy = tyle + yy - 2, gx = txle + xx - 2;
      float v = 0.f;
      if (gy >= 0 && gy < H && gx >= 0 && gx < W)
        v = in[(size_t)(b*C + chunk*32 + ci)*HW + gy*W + gx];
      sm[ci*248 + yy*20 + xx] = tf32r(v);
    }
    __syncthreads();
    #pragma unroll
    for (int kk = 0; kk < 9; kk++){
      int ky = kk/3, kx = kk - ky*3;
      #pragma unroll
      for (int c8 = 0; c8 < 4; c8++){
        uint32_t ab = sb + (uint32_t)(((c8*8 + t)*248 + (wm + 2*ky)*20 + g + 2*kx)*4);
        uint32_t a0 = ldss(ab);
        uint32_t a1 = ldss(ab + 32);
        uint32_t a2 = ldss(ab + 4*248*4);
        uint32_t a3 = ldss(ab + 4*248*4 + 32);
        const float2* wrow = wp + ((size_t)(kk*16 + chunk*4 + c8)*16)*32 + lane;
        #pragma unroll
        for (int j = 0; j < 16; j++){
          float2 bv = __ldg(wrow + j*32);
          mma_tf32(acc[j], a0, a1, a2, a3, __float_as_uint(bv.x), __float_as_uint(bv.y));
        }
      }
    }
  }

  int gx0 = txle + g, gy = tyle + wm;
  #pragma unroll
  for (int j = 0; j < 16; j++){
    int co = j*8 + 2*t;
    float2 bb = *(const float2*)&bias[co];
    size_t o0 = (size_t)(b*C + co)*HW + (size_t)gy*W + gx0;
    out[o0]        = fmaxf(acc[j][0] + bb.x, 0.f);
    out[o0 + HW]   = fmaxf(acc[j][1] + bb.y, 0.f);
    out[o0 + 8]    = fmaxf(acc[j][2] + bb.x, 0.f);
    out[o0 + HW+8] = fmaxf(acc[j][3] + bb.y, 0.f);
  }
}

// ---------------- 1x1 conv via tf32 mma + bias + residual ----------------
// block 256 thr, tile 128 pixels x 128 co, K=128. smem: [32ci][136]
#define C1M_SMEM (32*136*4)
__global__ __launch_bounds__(256) void conv1x1_mma_kernel(const float* __restrict__ hin,
                                                          const float2* __restrict__ wp,
                                                          const float* __restrict__ bias,
                                                          const float* __restrict__ x,
                                                          float* __restrict__ out){
  int blk = blockIdx.x;
  int b = blk / 288, hw0 = (blk - b*288)*128;
  extern __shared__ float sm[];
  int tid = threadIdx.x, lane = tid & 31, wm = tid >> 5;
  int t = lane & 3, g = lane >> 2;
  uint32_t sb = s2u(sm);
  float acc[16][4] = {};

  for (int chunk = 0; chunk < 4; chunk++){
    __syncthreads();
    for (int l = tid; l < 4096; l += 256){
      int ci = l >> 7, p = l & 127;
      sm[ci*136 + p] = tf32r(hin[(size_t)(b*C + chunk*32 + ci)*HW + hw0 + p]);
    }
    __syncthreads();
    #pragma unroll
    for (int c8 = 0; c8 < 4; c8++){
      uint32_t ab = sb + (uint32_t)(((c8*8 + t)*136 + wm*16 + g)*4);
      uint32_t a0 = ldss(ab);
      uint32_t a1 = ldss(ab + 32);
      uint32_t a2 = ldss(ab + 4*136*4);
      uint32_t a3 = ldss(ab + 4*136*4 + 32);
      const float2* wrow = wp + ((size_t)(chunk*4 + c8)*16)*32 + lane;
      #pragma unroll
      for (int j = 0; j < 16; j++){
        float2 bv = __ldg(wrow + j*32);
        mma_tf32(acc[j], a0, a1, a2, a3, __float_as_uint(bv.x), __float_as_uint(bv.y));
      }
    }
  }

  int p0 = hw0 + wm*16 + g;
  #pragma unroll
  for (int j = 0; j < 16; j++){
    int co = j*8 + 2*t;
    float2 bb = *(const float2*)&bias[co];
    size_t o0 = (size_t)(b*C + co)*HW + p0;
    out[o0]        = x[o0]        + acc[j][0] + bb.x;
    out[o0 + HW]   = x[o0 + HW]   + acc[j][1] + bb.y;
    out[o0 + 8]    = x[o0 + 8]    + acc[j][2] + bb.x;
    out[o0 + HW+8] = x[o0 + HW+8] + acc[j][3] + bb.y;
  }
}

// ---------------- launch ----------------
extern "C" void kernel_launch(void* const* d_in, const int* in_sizes, int n_in,
                              void* d_out, int out_size){
  const float* x   = (const float*)d_in[0];
  const float* wqk = (const float*)d_in[1];
  const float* w1  = (const float*)d_in[2];
  const float* b1  = (const float*)d_in[3];
  const float* w2  = (const float*)d_in[4];
  const float* b2  = (const float*)d_in[5];
  const float* w3  = (const float*)d_in[6];
  const float* b3  = (const float*)d_in[7];
  float* out = (float*)d_out;

  cudaFuncSetAttribute(prep_kernel,       cudaFuncAttributeMaxDynamicSharedMemorySize, PREP_SMEM);
  cudaFuncSetAttribute(attn_mma_kernel,   cudaFuncAttributeMaxDynamicSharedMemorySize, ATTN_SMEM);
  cudaFuncSetAttribute(conv3_mma_kernel,  cudaFuncAttributeMaxDynamicSharedMemorySize, C3_SMEM);
  cudaFuncSetAttribute(conv1x1_mma_kernel,cudaFuncAttributeMaxDynamicSharedMemorySize, C1M_SMEM);

  void *py_, *ph1_, *ph2_, *pw1_, *pw2_, *pw3_;
  cudaGetSymbolAddress(&py_,  g_y);
  cudaGetSymbolAddress(&ph1_, g_h1);
  cudaGetSymbolAddress(&ph2_, g_h2);
  cudaGetSymbolAddress(&pw1_, g_wp1);
  cudaGetSymbolAddress(&pw2_, g_wp2);
  cudaGetSymbolAddress(&pw3_, g_wp3);
  float*  py  = (float*)py_;
  float*  ph1 = (float*)ph1_;
  float*  ph2 = (float*)ph2_;
  float2* pw1 = (float2*)pw1_;
  float2* pw2 = (float2*)pw2_;
  float2* pw3 = (float2*)pw3_;

  prepack_kernel<<<608, 256>>>(w1, w2, w3);
  ln_partial_kernel<<<dim3(NB, BB), 256>>>(x);
  ln_final_kernel<<<BB, 256>>>();
  prep_kernel<<<(BF*NN)/64, 256, PREP_SMEM>>>(x, wqk);
  attn_mma_kernel<<<dim3(9, BF), 128, ATTN_SMEM>>>(x);
  conv3_mma_kernel<<<dim3(12, 24, 2), 256, C3_SMEM>>>(py,  pw1, b1, ph1);
  conv3_mma_kernel<<<dim3(12, 24, 2), 256, C3_SMEM>>>(ph1, pw2, b2, ph2);
  conv1x1_mma_kernel<<<576, 256, C1M_SMEM>>>(ph2, pw3, b3, x, out);
}

// round 7
// speedup vs baseline: 4.4347x; 1.2057x over previous
#include <cuda_runtime.h>
#include <cuda_bf16.h>
#include <math.h>
#include <stdint.h>

#define BB 2
#define C 128
#define H 192
#define W 192
#define HW (H*W)
#define CHW (C*HW)
#define E 128
#define SWID 24
#define NN 576
#define BF 128
#define NB 256

typedef unsigned long long ull;

// ---------------- mma helpers (base PTX, compute_103-safe) ----------------
__device__ __forceinline__ uint32_t s2u(const void* p){
  uint32_t a;
  asm("{ .reg .u64 t; cvta.to.shared.u64 t, %1; cvt.u32.u64 %0, t; }" : "=r"(a) : "l"(p));
  return a;
}
__device__ __forceinline__ void cp16(uint32_t d, const void* g){
  asm volatile("cp.async.cg.shared.global [%0], [%1], 16;" :: "r"(d), "l"(g));
}
#define CP_COMMIT() asm volatile("cp.async.commit_group;" ::: "memory")

__device__ __forceinline__ void ldsm4(uint32_t* r, uint32_t addr){
  asm volatile("ldmatrix.sync.aligned.m8n8.x4.shared.b16 {%0,%1,%2,%3}, [%4];"
    : "=r"(r[0]),"=r"(r[1]),"=r"(r[2]),"=r"(r[3]) : "r"(addr));
}
__device__ __forceinline__ void mma_bf16(float* c, const uint32_t* a, uint32_t b0, uint32_t b1){
  asm volatile("mma.sync.aligned.m16n8k16.row.col.f32.bf16.bf16.f32 "
    "{%0,%1,%2,%3}, {%4,%5,%6,%7}, {%8,%9}, {%0,%1,%2,%3};"
    : "+f"(c[0]),"+f"(c[1]),"+f"(c[2]),"+f"(c[3])
    : "r"(a[0]),"r"(a[1]),"r"(a[2]),"r"(a[3]), "r"(b0),"r"(b1));
}
__device__ __forceinline__ void mma_tf32(float* c, uint32_t a0, uint32_t a1, uint32_t a2,
                                         uint32_t a3, uint32_t b0, uint32_t b1){
  asm volatile("mma.sync.aligned.m16n8k8.row.col.f32.tf32.tf32.f32 "
    "{%0,%1,%2,%3}, {%4,%5,%6,%7}, {%8,%9}, {%0,%1,%2,%3};"
    : "+f"(c[0]),"+f"(c[1]),"+f"(c[2]),"+f"(c[3])
    : "r"(a0),"r"(a1),"r"(a2),"r"(a3), "r"(b0),"r"(b1));
}
__device__ __forceinline__ uint32_t packbf(float lo, float hi){
  uint32_t d; asm("cvt.rn.bf16x2.f32 %0, %1, %2;" : "=r"(d) : "f"(hi), "f"(lo)); return d;
}
__device__ __forceinline__ float tf32r(float v){
  uint32_t o; asm("cvt.rna.tf32.f32 %0, %1;" : "=r"(o) : "f"(v));
  return __uint_as_float(o);
}
__device__ __forceinline__ uint32_t ldss(uint32_t a){
  uint32_t v; asm volatile("ld.shared.b32 %0, [%1];" : "=r"(v) : "r"(a)); return v;
}

// ---------------- scratch (static device globals; no allocation) ----------------
__device__ float g_part[BB*NB*2];
__device__ float g_mv[4];
__device__ __nv_bfloat16 g_qkh[(size_t)BF*NN*E];   // [bf][n][e] unit-norm rows
__device__ __nv_bfloat16 g_vh [(size_t)BF*NN*C];   // [bf][c][n]
__device__ float g_y [(size_t)BB*CHW];
__device__ float g_h1[(size_t)BB*CHW];
__device__ float g_h2[(size_t)BB*CHW];
__device__ float2 g_wp1[73728];    // conv1 [kk][ci8][n8][lane]
__device__ float2 g_wp2[73728];    // conv2
__device__ float2 g_wp3[8192];     // 1x1 [ci8][n8][lane]
__device__ float2 g_wpqk[8192];    // wqk  [k8][n8][lane]

// ---------------- LayerNorm stats ----------------
__global__ void ln_partial_kernel(const float* __restrict__ x){
  int b = blockIdx.y;
  const float* xb = x + (size_t)b*CHW;
  float s = 0.f, ss = 0.f;
  for (int i = blockIdx.x*256 + threadIdx.x; i < CHW; i += NB*256){
    float v = xb[i]; s += v; ss += v*v;
  }
  #pragma unroll
  for (int o = 16; o; o >>= 1){
    s  += __shfl_xor_sync(0xffffffffu, s,  o);
    ss += __shfl_xor_sync(0xffffffffu, ss, o);
  }
  __shared__ float rs[8], rss[8];
  int warp = threadIdx.x >> 5, lane = threadIdx.x & 31;
  if (!lane){ rs[warp] = s; rss[warp] = ss; }
  __syncthreads();
  if (!threadIdx.x){
    float a = 0.f, c2 = 0.f;
    #pragma unroll
    for (int i = 0; i < 8; i++){ a += rs[i]; c2 += rss[i]; }
    g_part[(b*NB + blockIdx.x)*2]   = a;
    g_part[(b*NB + blockIdx.x)*2+1] = c2;
  }
}

__global__ void ln_final_kernel(){
  int b = blockIdx.x, t = threadIdx.x;
  float s  = g_part[(b*NB + t)*2];
  float ss = g_part[(b*NB + t)*2+1];
  #pragma unroll
  for (int o = 16; o; o >>= 1){
    s  += __shfl_xor_sync(0xffffffffu, s,  o);
    ss += __shfl_xor_sync(0xffffffffu, ss, o);
  }
  __shared__ float rs[8], rss[8];
  int warp = t >> 5, lane = t & 31;
  if (!lane){ rs[warp] = s; rss[warp] = ss; }
  __syncthreads();
  if (!t){
    float a = 0.f, c2 = 0.f;
    #pragma unroll
    for (int i = 0; i < 8; i++){ a += rs[i]; c2 += rss[i]; }
    float mean = a / (float)CHW;
    float var  = c2 / (float)CHW - mean*mean;
    g_mv[b*2]   = mean;
    g_mv[b*2+1] = rsqrtf(var + 1e-5f);
  }
}

// ---------------- weight prepack: fragment-order, tf32-rounded ----------------
__global__ void prepack_kernel(const float* __restrict__ w1, const float* __restrict__ w2,
                               const float* __restrict__ w3, const float* __restrict__ wqk){
  int i = blockIdx.x*256 + threadIdx.x;
  if (i < 2*73728){
    const float* w = (i < 73728) ? w1 : w2;
    float2* dst = (i < 73728) ? g_wp1 : g_wp2;
    int j = (i < 73728) ? i : i - 73728;
    int lane = j & 31, n8 = (j >> 5) & 15, ci8 = (j >> 9) & 15, kk = j >> 13;
    int t = lane & 3, g = lane >> 2;
    int co = n8*8 + g, ci = ci8*8 + t;
    float b0 = w[(co*128 + ci)*9 + kk];
    float b1 = w[(co*128 + ci + 4)*9 + kk];
    dst[j] = make_float2(tf32r(b0), tf32r(b1));
  } else if (i < 2*73728 + 8192){
    int j = i - 2*73728;
    int lane = j & 31, n8 = (j >> 5) & 15, ci8 = j >> 9;
    int t = lane & 3, g = lane >> 2;
    float b0 = w3[(n8*8 + g)*128 + ci8*8 + t];
    float b1 = w3[(n8*8 + g)*128 + ci8*8 + t + 4];
    g_wp3[j] = make_float2(tf32r(b0), tf32r(b1));
  } else {
    int j = i - 2*73728 - 8192;
    if (j < 8192){
      int lane = j & 31, n8 = (j >> 5) & 15, k8 = j >> 9;
      int t = lane & 3, g = lane >> 2;
      float b0 = wqk[(k8*8 + t)*E     + n8*8 + g];
      float b1 = wqk[(k8*8 + t + 4)*E + n8*8 + g];
      g_wpqk[j] = make_float2(tf32r(b0), tf32r(b1));
    }
  }
}

// ---------------- prep: unshuffle + tf32-mma qk projection + row L2-norm ----------------
// smem: xs [128 c][72] normalized tf32 (36864B) | ssq [64][2]
#define PREPM_SMEM (36864 + 512)
__global__ __launch_bounds__(256) void prep_mma_kernel(const float* __restrict__ x){
  int blk = blockIdx.x;
  int r0  = blk*64;
  int bf  = r0 / NN;
  int b   = bf >> 6, k = bf & 63, dy = k >> 3, dx = k & 7;
  float mean = g_mv[b*2], rstd = g_mv[b*2+1];
  extern __shared__ float sm[];
  float* xs  = sm;                 // [c][72]
  float* ssq = sm + 9216;          // [64][2]
  int tid = threadIdx.x;
  int lane = tid & 31, wm = tid >> 5;
  int t = lane & 3, g = lane >> 2;
  uint32_t sb = s2u(sm);

  int n0 = r0 - bf*NN;
  for (int l = tid; l < 8192; l += 256){
    int c = l >> 6, i = l & 63;
    int n  = n0 + i;
    int sh = n / SWID, swp = n - sh*SWID;
    int h  = sh*8 + dy, w = swp*8 + dx;
    float xv = x[(size_t)(b*C + c)*HW + h*W + w];
    g_vh[((size_t)bf*C + c)*NN + n] = __float2bfloat16(xv);
    xs[c*72 + i] = tf32r((xv - mean)*rstd);
  }
  __syncthreads();

  // GEMM: [64 rows x 128 e] = xs^T(row-major rows=n) * wqk. 8 warps:
  // rg = wm&3 (16-row group), eh = wm>>2 (64-e half, 8 n8 tiles)
  int rg = wm & 3, eh = wm >> 2;
  float acc[8][4] = {};
  #pragma unroll
  for (int k8 = 0; k8 < 16; k8++){
    uint32_t ab = sb + (uint32_t)(((k8*8 + t)*72 + rg*16 + g)*4);
    uint32_t a0 = ldss(ab);
    uint32_t a1 = ldss(ab + 32);
    uint32_t a2 = ldss(ab + 4*72*4);
    uint32_t a3 = ldss(ab + 4*72*4 + 32);
    const float2* wrow = g_wpqk + (size_t)(k8*16 + eh*8)*32 + lane;
    #pragma unroll
    for (int j = 0; j < 8; j++){
      float2 bv = __ldg(wrow + j*32);
      mma_tf32(acc[j], a0, a1, a2, a3, __float_as_uint(bv.x), __float_as_uint(bv.y));
    }
  }

  // row L2 norms: per-thread partial over 16 e-values per row
  float s0 = 0.f, s1 = 0.f;
  #pragma unroll
  for (int j = 0; j < 8; j++){
    s0 += acc[j][0]*acc[j][0] + acc[j][1]*acc[j][1];
    s1 += acc[j][2]*acc[j][2] + acc[j][3]*acc[j][3];
  }
  s0 += __shfl_xor_sync(0xffffffffu, s0, 1);
  s0 += __shfl_xor_sync(0xffffffffu, s0, 2);
  s1 += __shfl_xor_sync(0xffffffffu, s1, 1);
  s1 += __shfl_xor_sync(0xffffffffu, s1, 2);
  if (t == 0){
    ssq[(rg*16 + g)*2 + eh]     = s0;
    ssq[(rg*16 + g + 8)*2 + eh] = s1;
  }
  __syncthreads();
  int row0 = rg*16 + g, row1 = row0 + 8;
  float inv0 = 1.f/(sqrtf(ssq[row0*2] + ssq[row0*2+1]) + 1e-8f);
  float inv1 = 1.f/(sqrtf(ssq[row1*2] + ssq[row1*2+1]) + 1e-8f);

  __nv_bfloat16* q0 = g_qkh + (size_t)(r0 + row0)*E + eh*64 + 2*t;
  __nv_bfloat16* q1 = g_qkh + (size_t)(r0 + row1)*E + eh*64 + 2*t;
  #pragma unroll
  for (int j = 0; j < 8; j++){
    *(uint32_t*)(q0 + j*8) = packbf(acc[j][0]*inv0, acc[j][1]*inv0);
    *(uint32_t*)(q1 + j*8) = packbf(acc[j][2]*inv1, acc[j][3]*inv1);
  }
}

// ---------------- attention: mma.sync bf16 flash, no-max softmax ----------------
#define AOFF_Q  0
#define AOFF_K0 16384
#define AOFF_K1 32768
#define AOFF_V0 49152
#define AOFF_V1 65536
#define ATTN_SMEM 81920

__device__ __forceinline__ void load_kv(uint32_t sb, const __nv_bfloat16* qsrc,
                                        const __nv_bfloat16* vsrc, int jt, int tid){
  uint32_t kb = sb + ((jt & 1) ? AOFF_K1 : AOFF_K0);
  uint32_t vb = sb + ((jt & 1) ? AOFF_V1 : AOFF_V0);
  const __nv_bfloat16* ks = qsrc + (size_t)jt*64*E;
  #pragma unroll
  for (int r = 0; r < 8; r++){
    int idx = tid + 128*r;
    int row = idx >> 4, ch = idx & 15;
    cp16(kb + row*256 + ((ch ^ (row & 7))*16), ks + (size_t)row*E + ch*8);
  }
  const __nv_bfloat16* vs = vsrc + jt*64;
  #pragma unroll
  for (int r = 0; r < 8; r++){
    int idx = tid + 128*r;
    int row = idx >> 3, ch = idx & 7;
    cp16(vb + row*128 + ((ch ^ (row & 7))*16), vs + (size_t)row*NN + ch*8);
  }
  CP_COMMIT();
}

__global__ __launch_bounds__(128) void attn_mma_kernel(const float* __restrict__ x){
  extern __shared__ char smc[];
  const int tid = threadIdx.x;
  const int lane = tid & 31, w = tid >> 5;
  const int rt = blockIdx.x, bf = blockIdx.y;
  const int r0 = rt*64;
  const __nv_bfloat16* qsrc = g_qkh + (size_t)bf*NN*E;
  const __nv_bfloat16* vsrc = g_vh  + (size_t)bf*C*NN;
  uint32_t sb = s2u(smc);

  {
    const __nv_bfloat16* qs = qsrc + (size_t)r0*E;
    #pragma unroll
    for (int r = 0; r < 8; r++){
      int idx = tid + 128*r;
      int row = idx >> 4, ch = idx & 15;
      cp16(sb + AOFF_Q + row*256 + ((ch ^ (row & 7))*16), qs + (size_t)row*E + ch*8);
    }
    CP_COMMIT();
  }
  load_kv(sb, qsrc, vsrc, 0, tid);
  asm volatile("cp.async.wait_group 1;" ::: "memory");
  __syncthreads();

  uint32_t qa[8][4];
  #pragma unroll
  for (int kk = 0; kk < 8; kk++){
    int row = w*16 + (lane & 15);
    int ch  = kk*2 + (lane >> 4);
    ldsm4(qa[kk], sb + AOFF_Q + row*256 + ((ch ^ (row & 7))*16));
  }

  float oacc[16][4];
  #pragma unroll
  for (int i = 0; i < 16; i++){ oacc[i][0]=0.f; oacc[i][1]=0.f; oacc[i][2]=0.f; oacc[i][3]=0.f; }
  float rsum0 = 0.f, rsum1 = 0.f;
  const float invsE = 0.08838834764831845f;

  for (int jt = 0; jt < 9; jt++){
    __syncthreads();
    if (jt < 8){
      load_kv(sb, qsrc, vsrc, jt+1, tid);
      asm volatile("cp.async.wait_group 1;" ::: "memory");
    } else {
      asm volatile("cp.async.wait_group 0;" ::: "memory");
    }
    __syncthreads();

    uint32_t kbase = sb + ((jt & 1) ? AOFF_K1 : AOFF_K0);
    uint32_t vbase = sb + ((jt & 1) ? AOFF_V1 : AOFF_V0);

    float sc[8][4];
    #pragma unroll
    for (int i = 0; i < 8; i++){ sc[i][0]=0.f; sc[i][1]=0.f; sc[i][2]=0.f; sc[i][3]=0.f; }
    #pragma unroll
    for (int jp = 0; jp < 4; jp++){
      #pragma unroll
      for (int kk = 0; kk < 8; kk++){
        uint32_t kb[4];
        int row = jp*16 + (lane & 15);
        int ch  = kk*2 + (lane >> 4);
        ldsm4(kb, kbase + row*256 + ((ch ^ (row & 7))*16));
        mma_bf16(sc[2*jp],   qa[kk], kb[0], kb[2]);
        mma_bf16(sc[2*jp+1], qa[kk], kb[1], kb[3]);
      }
    }

    uint32_t pa[4][4];
    #pragma unroll
    for (int j = 0; j < 8; j++){
      float p0 = __expf(sc[j][0]*invsE), p1 = __expf(sc[j][1]*invsE);
      float p2 = __expf(sc[j][2]*invsE), p3 = __expf(sc[j][3]*invsE);
      rsum0 += p0 + p1; rsum1 += p2 + p3;
      int kk = j >> 1;
      if ((j & 1) == 0){ pa[kk][0] = packbf(p0,p1); pa[kk][1] = packbf(p2,p3); }
      else             { pa[kk][2] = packbf(p0,p1); pa[kk][3] = packbf(p2,p3); }
    }

    #pragma unroll
    for (int jnp = 0; jnp < 8; jnp++){
      #pragma unroll
      for (int kk = 0; kk < 4; kk++){
        uint32_t vb[4];
        int row = jnp*16 + (lane & 15);
        int ch  = kk*2 + (lane >> 4);
        ldsm4(vb, vbase + row*128 + ((ch ^ (row & 7))*16));
        mma_bf16(oacc[2*jnp],   pa[kk], vb[0], vb[2]);
        mma_bf16(oacc[2*jnp+1], pa[kk], vb[1], vb[3]);
      }
    }
  }

  rsum0 += __shfl_xor_sync(0xffffffffu, rsum0, 1);
  rsum0 += __shfl_xor_sync(0xffffffffu, rsum0, 2);
  rsum1 += __shfl_xor_sync(0xffffffffu, rsum1, 1);
  rsum1 += __shfl_xor_sync(0xffffffffu, rsum1, 2);
  float inv0 = 1.f/rsum0, inv1 = 1.f/rsum1;

  int g = lane >> 2, t4 = lane & 3;
  int b = bf >> 6, kk2 = bf & 63, dy = kk2 >> 3, dx = kk2 & 7;
  int nA = r0 + w*16 + g;
  int nB = nA + 8;
  int shA = nA / SWID, swA = nA - shA*SWID;
  int shB = nB / SWID, swB = nB - shB*SWID;
  size_t baseA = (size_t)b*CHW + (size_t)(shA*8 + dy)*W + (swA*8 + dx);
  size_t baseB = (size_t)b*CHW + (size_t)(shB*8 + dy)*W + (swB*8 + dx);
  #pragma unroll
  for (int jn = 0; jn < 16; jn++){
    int c0 = jn*8 + 2*t4;
    size_t giA = baseA + (size_t)c0*HW;
    size_t giB = baseB + (size_t)c0*HW;
    g_y[giA]    = x[giA]    + oacc[jn][0]*inv0;
    g_y[giA+HW] = x[giA+HW] + oacc[jn][1]*inv0;
    g_y[giB]    = x[giB]    + oacc[jn][2]*inv1;
    g_y[giB+HW] = x[giB+HW] + oacc[jn][3]*inv1;
  }
}

// ---------------- 3x3 dilated conv via tf32 mma implicit GEMM ----------------
#define C3_SMEM (7936*4)
__global__ __launch_bounds__(256) void conv3_mma_kernel(const float* __restrict__ in,
                                                        const float2* __restrict__ wp,
                                                        const float* __restrict__ bias,
                                                        float* __restrict__ out){
  int txle = blockIdx.x*16, tyle = blockIdx.y*8, b = blockIdx.z;
  extern __shared__ float sm[];
  int tid = threadIdx.x, lane = tid & 31, wm = tid >> 5;
  int t = lane & 3, g = lane >> 2;
  uint32_t sb = s2u(sm);
  float acc[16][4] = {};

  for (int chunk = 0; chunk < 4; chunk++){
    __syncthreads();
    for (int l = tid; l < 7680; l += 256){
      int ci = l / 240, r = l - ci*240, yy = r / 20, xx = r - yy*20;
      int gy = tyle + yy - 2, gx = txle + xx - 2;
      float v = 0.f;
      if (gy >= 0 && gy < H && gx >= 0 && gx < W)
        v = in[(size_t)(b*C + chunk*32 + ci)*HW + gy*W + gx];
      sm[ci*248 + yy*20 + xx] = tf32r(v);
    }
    __syncthreads();
    #pragma unroll
    for (int kk = 0; kk < 9; kk++){
      int ky = kk/3, kx = kk - ky*3;
      #pragma unroll
      for (int c8 = 0; c8 < 4; c8++){
        uint32_t ab = sb + (uint32_t)(((c8*8 + t)*248 + (wm + 2*ky)*20 + g + 2*kx)*4);
        uint32_t a0 = ldss(ab);
        uint32_t a1 = ldss(ab + 32);
        uint32_t a2 = ldss(ab + 4*248*4);
        uint32_t a3 = ldss(ab + 4*248*4 + 32);
        const float2* wrow = wp + ((size_t)(kk*16 + chunk*4 + c8)*16)*32 + lane;
        #pragma unroll
        for (int j = 0; j < 16; j++){
          float2 bv = __ldg(wrow + j*32);
          mma_tf32(acc[j], a0, a1, a2, a3, __float_as_uint(bv.x), __float_as_uint(bv.y));
        }
      }
    }
  }

  int gx0 = txle + g, gy = tyle + wm;
  #pragma unroll
  for (int j = 0; j < 16; j++){
    int co = j*8 + 2*t;
    float2 bb = *(const float2*)&bias[co];
    size_t o0 = (size_t)(b*C + co)*HW + (size_t)gy*W + gx0;
    out[o0]        = fmaxf(acc[j][0] + bb.x, 0.f);
    out[o0 + HW]   = fmaxf(acc[j][1] + bb.y, 0.f);
    out[o0 + 8]    = fmaxf(acc[j][2] + bb.x, 0.f);
    out[o0 + HW+8] = fmaxf(acc[j][3] + bb.y, 0.f);
  }
}

// ---------------- 1x1 conv via tf32 mma + bias + residual ----------------
#define C1M_SMEM (32*136*4)
__global__ __launch_bounds__(256) void conv1x1_mma_kernel(const float* __restrict__ hin,
                                                          const float2* __restrict__ wp,
                                                          const float* __restrict__ bias,
                                                          const float* __restrict__ x,
                                                          float* __restrict__ out){
  int blk = blockIdx.x;
  int b = blk / 288, hw0 = (blk - b*288)*128;
  extern __shared__ float sm[];
  int tid = threadIdx.x, lane = tid & 31, wm = tid >> 5;
  int t = lane & 3, g = lane >> 2;
  uint32_t sb = s2u(sm);
  float acc[16][4] = {};

  for (int chunk = 0; chunk < 4; chunk++){
    __syncthreads();
    for (int l = tid; l < 4096; l += 256){
      int ci = l >> 7, p = l & 127;
      sm[ci*136 + p] = tf32r(hin[(size_t)(b*C + chunk*32 + ci)*HW + hw0 + p]);
    }
    __syncthreads();
    #pragma unroll
    for (int c8 = 0; c8 < 4; c8++){
      uint32_t ab = sb + (uint32_t)(((c8*8 + t)*136 + wm*16 + g)*4);
      uint32_t a0 = ldss(ab);
      uint32_t a1 = ldss(ab + 32);
      uint32_t a2 = ldss(ab + 4*136*4);
      uint32_t a3 = ldss(ab + 4*136*4 + 32);
      const float2* wrow = wp + ((size_t)(chunk*4 + c8)*16)*32 + lane;
      #pragma unroll
      for (int j = 0; j < 16; j++){
        float2 bv = __ldg(wrow + j*32);
        mma_tf32(acc[j], a0, a1, a2, a3, __float_as_uint(bv.x), __float_as_uint(bv.y));
      }
    }
  }

  int p0 = hw0 + wm*16 + g;
  #pragma unroll
  for (int j = 0; j < 16; j++){
    int co = j*8 + 2*t;
    float2 bb = *(const float2*)&bias[co];
    size_t o0 = (size_t)(b*C + co)*HW + p0;
    out[o0]        = x[o0]        + acc[j][0] + bb.x;
    out[o0 + HW]   = x[o0 + HW]   + acc[j][1] + bb.y;
    out[o0 + 8]    = x[o0 + 8]    + acc[j][2] + bb.x;
    out[o0 + HW+8] = x[o0 + HW+8] + acc[j][3] + bb.y;
  }
}

// ---------------- launch ----------------
extern "C" void kernel_launch(void* const* d_in, const int* in_sizes, int n_in,
                              void* d_out, int out_size){
  const float* x   = (const float*)d_in[0];
  const float* wqk = (const float*)d_in[1];
  const float* w1  = (const float*)d_in[2];
  const float* b1  = (const float*)d_in[3];
  const float* w2  = (const float*)d_in[4];
  const float* b2  = (const float*)d_in[5];
  const float* w3  = (const float*)d_in[6];
  const float* b3  = (const float*)d_in[7];
  float* out = (float*)d_out;

  cudaFuncSetAttribute(prep_mma_kernel,   cudaFuncAttributeMaxDynamicSharedMemorySize, PREPM_SMEM);
  cudaFuncSetAttribute(attn_mma_kernel,   cudaFuncAttributeMaxDynamicSharedMemorySize, ATTN_SMEM);
  cudaFuncSetAttribute(conv3_mma_kernel,  cudaFuncAttributeMaxDynamicSharedMemorySize, C3_SMEM);
  cudaFuncSetAttribute(conv1x1_mma_kernel,cudaFuncAttributeMaxDynamicSharedMemorySize, C1M_SMEM);

  void *py_, *ph1_, *ph2_, *pw1_, *pw2_, *pw3_;
  cudaGetSymbolAddress(&py_,  g_y);
  cudaGetSymbolAddress(&ph1_, g_h1);
  cudaGetSymbolAddress(&ph2_, g_h2);
  cudaGetSymbolAddress(&pw1_, g_wp1);
  cudaGetSymbolAddress(&pw2_, g_wp2);
  cudaGetSymbolAddress(&pw3_, g_wp3);
  float*  py  = (float*)py_;
  float*  ph1 = (float*)ph1_;
  float*  ph2 = (float*)ph2_;
  float2* pw1 = (float2*)pw1_;
  float2* pw2 = (float2*)pw2_;
  float2* pw3 = (float2*)pw3_;

  prepack_kernel<<<640, 256>>>(w1, w2, w3, wqk);
  ln_partial_kernel<<<dim3(NB, BB), 256>>>(x);
  ln_final_kernel<<<BB, 256>>>();
  prep_mma_kernel<<<(BF*NN)/64, 256, PREPM_SMEM>>>(x);
  attn_mma_kernel<<<dim3(9, BF), 128, ATTN_SMEM>>>(x);
  conv3_mma_kernel<<<dim3(12, 24, 2), 256, C3_SMEM>>>(py,  pw1, b1, ph1);
  conv3_mma_kernel<<<dim3(12, 24, 2), 256, C3_SMEM>>>(ph1, pw2, b2, ph2);
  conv1x1_mma_kernel<<<576, 256, C1M_SMEM>>>(ph2, pw3, b3, x, out);
}

// round 8
// speedup vs baseline: 4.6322x; 1.0445x over previous
#include <cuda_runtime.h>
#include <cuda_bf16.h>
#include <math.h>
#include <stdint.h>

#define BB 2
#define C 128
#define H 192
#define W 192
#define HW (H*W)
#define CHW (C*HW)
#define E 128
#define SWID 24
#define NN 576
#define BF 128
#define NB 256

// ---------------- mma helpers (base PTX, compute_103-safe) ----------------
__device__ __forceinline__ uint32_t s2u(const void* p){
  uint32_t a;
  asm("{ .reg .u64 t; cvta.to.shared.u64 t, %1; cvt.u32.u64 %0, t; }" : "=r"(a) : "l"(p));
  return a;
}
__device__ __forceinline__ void cp16(uint32_t d, const void* g){
  asm volatile("cp.async.cg.shared.global [%0], [%1], 16;" :: "r"(d), "l"(g));
}
#define CP_COMMIT() asm volatile("cp.async.commit_group;" ::: "memory")

__device__ __forceinline__ void ldsm4(uint32_t* r, uint32_t addr){
  asm volatile("ldmatrix.sync.aligned.m8n8.x4.shared.b16 {%0,%1,%2,%3}, [%4];"
    : "=r"(r[0]),"=r"(r[1]),"=r"(r[2]),"=r"(r[3]) : "r"(addr));
}
__device__ __forceinline__ void mma_bf16(float* c, const uint32_t* a, uint32_t b0, uint32_t b1){
  asm volatile("mma.sync.aligned.m16n8k16.row.col.f32.bf16.bf16.f32 "
    "{%0,%1,%2,%3}, {%4,%5,%6,%7}, {%8,%9}, {%0,%1,%2,%3};"
    : "+f"(c[0]),"+f"(c[1]),"+f"(c[2]),"+f"(c[3])
    : "r"(a[0]),"r"(a[1]),"r"(a[2]),"r"(a[3]), "r"(b0),"r"(b1));
}
__device__ __forceinline__ void mma_tf32(float* c, uint32_t a0, uint32_t a1, uint32_t a2,
                                         uint32_t a3, uint32_t b0, uint32_t b1){
  asm volatile("mma.sync.aligned.m16n8k8.row.col.f32.tf32.tf32.f32 "
    "{%0,%1,%2,%3}, {%4,%5,%6,%7}, {%8,%9}, {%0,%1,%2,%3};"
    : "+f"(c[0]),"+f"(c[1]),"+f"(c[2]),"+f"(c[3])
    : "r"(a0),"r"(a1),"r"(a2),"r"(a3), "r"(b0),"r"(b1));
}
__device__ __forceinline__ void mma_tf32_f4(float* cA, float* cB, uint32_t a0, uint32_t a1,
                                            uint32_t a2, uint32_t a3, float4 bv){
  mma_tf32(cA, a0, a1, a2, a3, __float_as_uint(bv.x), __float_as_uint(bv.y));
  mma_tf32(cB, a0, a1, a2, a3, __float_as_uint(bv.z), __float_as_uint(bv.w));
}
__device__ __forceinline__ uint32_t packbf(float lo, float hi){
  uint32_t d; asm("cvt.rn.bf16x2.f32 %0, %1, %2;" : "=r"(d) : "f"(hi), "f"(lo)); return d;
}
__device__ __forceinline__ float tf32r(float v){
  uint32_t o; asm("cvt.rna.tf32.f32 %0, %1;" : "=r"(o) : "f"(v));
  return __uint_as_float(o);
}
__device__ __forceinline__ uint32_t ldss(uint32_t a){
  uint32_t v; asm volatile("ld.shared.b32 %0, [%1];" : "=r"(v) : "r"(a)); return v;
}

// ---------------- scratch (static device globals; no allocation) ----------------
__device__ float g_part[BB*NB*2];
__device__ float g_mv[4];
__device__ __nv_bfloat16 g_qkh[(size_t)BF*NN*E];   // [bf][n][e] unit-norm rows
__device__ __nv_bfloat16 g_vh [(size_t)BF*NN*C];   // [bf][c][n]
__device__ float g_y [(size_t)BB*CHW];
__device__ float g_h1[(size_t)BB*CHW];
__device__ float g_h2[(size_t)BB*CHW];
__device__ float4 g_wq1[36864];   // conv1 [kk*16+ci8][jp][lane] paired n8 frags
__device__ float4 g_wq2[36864];   // conv2
__device__ float4 g_wq3[4096];    // 1x1  [ci8][jp][lane]
__device__ float4 g_wq4[4096];    // wqk  [k8*2+eh][jp][lane]

// ---------------- LayerNorm stats ----------------
__global__ void ln_partial_kernel(const float* __restrict__ x){
  int b = blockIdx.y;
  const float* xb = x + (size_t)b*CHW;
  float s = 0.f, ss = 0.f;
  for (int i = blockIdx.x*256 + threadIdx.x; i < CHW; i += NB*256){
    float v = xb[i]; s += v; ss += v*v;
  }
  #pragma unroll
  for (int o = 16; o; o >>= 1){
    s  += __shfl_xor_sync(0xffffffffu, s,  o);
    ss += __shfl_xor_sync(0xffffffffu, ss, o);
  }
  __shared__ float rs[8], rss[8];
  int warp = threadIdx.x >> 5, lane = threadIdx.x & 31;
  if (!lane){ rs[warp] = s; rss[warp] = ss; }
  __syncthreads();
  if (!threadIdx.x){
    float a = 0.f, c2 = 0.f;
    #pragma unroll
    for (int i = 0; i < 8; i++){ a += rs[i]; c2 += rss[i]; }
    g_part[(b*NB + blockIdx.x)*2]   = a;
    g_part[(b*NB + blockIdx.x)*2+1] = c2;
  }
}

__global__ void ln_final_kernel(){
  int b = blockIdx.x, t = threadIdx.x;
  float s  = g_part[(b*NB + t)*2];
  float ss = g_part[(b*NB + t)*2+1];
  #pragma unroll
  for (int o = 16; o; o >>= 1){
    s  += __shfl_xor_sync(0xffffffffu, s,  o);
    ss += __shfl_xor_sync(0xffffffffu, ss, o);
  }
  __shared__ float rs[8], rss[8];
  int warp = t >> 5, lane = t & 31;
  if (!lane){ rs[warp] = s; rss[warp] = ss; }
  __syncthreads();
  if (!t){
    float a = 0.f, c2 = 0.f;
    #pragma unroll
    for (int i = 0; i < 8; i++){ a += rs[i]; c2 += rss[i]; }
    float mean = a / (float)CHW;
    float var  = c2 / (float)CHW - mean*mean;
    g_mv[b*2]   = mean;
    g_mv[b*2+1] = rsqrtf(var + 1e-5f);
  }
}

// ---------------- weight prepack: paired-fragment float4, tf32-rounded ----------------
// total threads: 2*36864 + 4096 + 4096 = 81920
__global__ void prepack_kernel(const float* __restrict__ w1, const float* __restrict__ w2,
                               const float* __restrict__ w3, const float* __restrict__ wqk){
  int i = blockIdx.x*256 + threadIdx.x;
  if (i < 2*36864){
    const float* w = (i < 36864) ? w1 : w2;
    float4* dst = (i < 36864) ? g_wq1 : g_wq2;
    int j = (i < 36864) ? i : i - 36864;
    int lane = j & 31, jp = (j >> 5) & 7, kidx = j >> 8;     // kidx < 144
    int kk = kidx >> 4, ci8 = kidx & 15;
    int t = lane & 3, g = lane >> 2;
    int ci = ci8*8 + t;
    int coA = (2*jp)*8 + g, coB = (2*jp+1)*8 + g;
    dst[j] = make_float4(tf32r(w[(coA*128 + ci)*9 + kk]),
                         tf32r(w[(coA*128 + ci + 4)*9 + kk]),
                         tf32r(w[(coB*128 + ci)*9 + kk]),
                         tf32r(w[(coB*128 + ci + 4)*9 + kk]));
  } else if (i < 2*36864 + 4096){
    int j = i - 2*36864;
    int lane = j & 31, jp = (j >> 5) & 7, ci8 = j >> 8;
    int t = lane & 3, g = lane >> 2;
    int coA = (2*jp)*8 + g, coB = (2*jp+1)*8 + g;
    g_wq3[j] = make_float4(tf32r(w3[coA*128 + ci8*8 + t]),
                           tf32r(w3[coA*128 + ci8*8 + t + 4]),
                           tf32r(w3[coB*128 + ci8*8 + t]),
                           tf32r(w3[coB*128 + ci8*8 + t + 4]));
  } else {
    int j = i - 2*36864 - 4096;
    if (j < 4096){
      int lane = j & 31, jp = (j >> 5) & 3, e2 = (j >> 7) & 1, k8 = j >> 8;
      int t = lane & 3, g = lane >> 2;
      int n8a = e2*8 + 2*jp, n8b = n8a + 1;
      g_wq4[j] = make_float4(tf32r(wqk[(k8*8 + t)*E     + n8a*8 + g]),
                             tf32r(wqk[(k8*8 + t + 4)*E + n8a*8 + g]),
                             tf32r(wqk[(k8*8 + t)*E     + n8b*8 + g]),
                             tf32r(wqk[(k8*8 + t + 4)*E + n8b*8 + g]));
    }
  }
}

// ---------------- prep: unshuffle + tf32-mma qk projection + row L2-norm ----------------
#define PREPM_SMEM (36864 + 512)
__global__ __launch_bounds__(256) void prep_mma_kernel(const float* __restrict__ x){
  int blk = blockIdx.x;
  int r0  = blk*64;
  int bf  = r0 / NN;
  int b   = bf >> 6, k = bf & 63, dy = k >> 3, dx = k & 7;
  float mean = g_mv[b*2], rstd = g_mv[b*2+1];
  extern __shared__ float sm[];
  float* xs  = sm;                 // [c][72]
  float* ssq = sm + 9216;          // [64][2]
  int tid = threadIdx.x;
  int lane = tid & 31, wm = tid >> 5;
  int t = lane & 3, g = lane >> 2;
  uint32_t sb = s2u(sm);

  int n0 = r0 - bf*NN;
  for (int l = tid; l < 8192; l += 256){
    int c = l >> 6, i = l & 63;
    int n  = n0 + i;
    int sh = n / SWID, swp = n - sh*SWID;
    int h  = sh*8 + dy, w = swp*8 + dx;
    float xv = x[(size_t)(b*C + c)*HW + h*W + w];
    g_vh[((size_t)bf*C + c)*NN + n] = __float2bfloat16(xv);
    xs[c*72 + i] = tf32r((xv - mean)*rstd);
  }
  __syncthreads();

  int rg = wm & 3, eh = wm >> 2;
  float acc[8][4] = {};
  #pragma unroll
  for (int k8 = 0; k8 < 16; k8++){
    uint32_t ab = sb + (uint32_t)(((k8*8 + t)*72 + rg*16 + g)*4);
    uint32_t a0 = ldss(ab);
    uint32_t a1 = ldss(ab + 32);
    uint32_t a2 = ldss(ab + 4*72*4);
    uint32_t a3 = ldss(ab + 4*72*4 + 32);
    const float4* wrow = g_wq4 + (size_t)((k8*2 + eh)*4)*32 + lane;
    #pragma unroll
    for (int jp = 0; jp < 4; jp++){
      float4 bv = __ldg(wrow + jp*32);
      mma_tf32_f4(acc[2*jp], acc[2*jp+1], a0, a1, a2, a3, bv);
    }
  }

  float s0 = 0.f, s1 = 0.f;
  #pragma unroll
  for (int j = 0; j < 8; j++){
    s0 += acc[j][0]*acc[j][0] + acc[j][1]*acc[j][1];
    s1 += acc[j][2]*acc[j][2] + acc[j][3]*acc[j][3];
  }
  s0 += __shfl_xor_sync(0xffffffffu, s0, 1);
  s0 += __shfl_xor_sync(0xffffffffu, s0, 2);
  s1 += __shfl_xor_sync(0xffffffffu, s1, 1);
  s1 += __shfl_xor_sync(0xffffffffu, s1, 2);
  if (t == 0){
    ssq[(rg*16 + g)*2 + eh]     = s0;
    ssq[(rg*16 + g + 8)*2 + eh] = s1;
  }
  __syncthreads();
  int row0 = rg*16 + g, row1 = row0 + 8;
  float inv0 = 1.f/(sqrtf(ssq[row0*2] + ssq[row0*2+1]) + 1e-8f);
  float inv1 = 1.f/(sqrtf(ssq[row1*2] + ssq[row1*2+1]) + 1e-8f);

  __nv_bfloat16* q0 = g_qkh + (size_t)(r0 + row0)*E + eh*64 + 2*t;
  __nv_bfloat16* q1 = g_qkh + (size_t)(r0 + row1)*E + eh*64 + 2*t;
  #pragma unroll
  for (int j = 0; j < 8; j++){
    *(uint32_t*)(q0 + j*8) = packbf(acc[j][0]*inv0, acc[j][1]*inv0);
    *(uint32_t*)(q1 + j*8) = packbf(acc[j][2]*inv1, acc[j][3]*inv1);
  }
}

// ---------------- attention: mma.sync bf16 flash, single-V-buffer ----------------
// smem: Q 16K | K0 16K | K1 16K | V 16K = 64K  -> 3 blocks/SM
#define AOFF_Q  0
#define AOFF_K0 16384
#define AOFF_K1 32768
#define AOFF_V  49152
#define ATTN_SMEM 65536

__device__ __forceinline__ void load_k(uint32_t sb, const __nv_bfloat16* qsrc, int jt, int tid){
  uint32_t kb = sb + ((jt & 1) ? AOFF_K1 : AOFF_K0);
  const __nv_bfloat16* ks = qsrc + (size_t)jt*64*E;
  #pragma unroll
  for (int r = 0; r < 8; r++){
    int idx = tid + 128*r;
    int row = idx >> 4, ch = idx & 15;
    cp16(kb + row*256 + ((ch ^ (row & 7))*16), ks + (size_t)row*E + ch*8);
  }
  CP_COMMIT();
}
__device__ __forceinline__ void load_v(uint32_t sb, const __nv_bfloat16* vsrc, int jt, int tid){
  uint32_t vb = sb + AOFF_V;
  const __nv_bfloat16* vs = vsrc + jt*64;
  #pragma unroll
  for (int r = 0; r < 8; r++){
    int idx = tid + 128*r;
    int row = idx >> 3, ch = idx & 7;
    cp16(vb + row*128 + ((ch ^ (row & 7))*16), vs + (size_t)row*NN + ch*8);
  }
  CP_COMMIT();
}

__global__ __launch_bounds__(128) void attn_mma_kernel(const float* __restrict__ x){
  extern __shared__ char smc[];
  const int tid = threadIdx.x;
  const int lane = tid & 31, w = tid >> 5;
  const int rt = blockIdx.x, bf = blockIdx.y;
  const int r0 = rt*64;
  const __nv_bfloat16* qsrc = g_qkh + (size_t)bf*NN*E;
  const __nv_bfloat16* vsrc = g_vh  + (size_t)bf*C*NN;
  uint32_t sb = s2u(smc);

  {
    const __nv_bfloat16* qs = qsrc + (size_t)r0*E;
    #pragma unroll
    for (int r = 0; r < 8; r++){
      int idx = tid + 128*r;
      int row = idx >> 4, ch = idx & 15;
      cp16(sb + AOFF_Q + row*256 + ((ch ^ (row & 7))*16), qs + (size_t)row*E + ch*8);
    }
    CP_COMMIT();
  }
  load_k(sb, qsrc, 0, tid);
  asm volatile("cp.async.wait_group 0;" ::: "memory");
  __syncthreads();

  uint32_t qa[8][4];
  #pragma unroll
  for (int kk = 0; kk < 8; kk++){
    int row = w*16 + (lane & 15);
    int ch  = kk*2 + (lane >> 4);
    ldsm4(qa[kk], sb + AOFF_Q + row*256 + ((ch ^ (row & 7))*16));
  }

  float oacc[16][4];
  #pragma unroll
  for (int i = 0; i < 16; i++){ oacc[i][0]=0.f; oacc[i][1]=0.f; oacc[i][2]=0.f; oacc[i][3]=0.f; }
  float rsum0 = 0.f, rsum1 = 0.f;
  const float invsE = 0.08838834764831845f;

  for (int jt = 0; jt < 9; jt++){
    __syncthreads();                       // V + K(jt+1) buffers free
    if (jt < 8) load_k(sb, qsrc, jt+1, tid);
    load_v(sb, vsrc, jt, tid);
    if (jt < 8) asm volatile("cp.async.wait_group 2;" ::: "memory");  // K(jt) done
    else        asm volatile("cp.async.wait_group 1;" ::: "memory");
    __syncthreads();

    uint32_t kbase = sb + ((jt & 1) ? AOFF_K1 : AOFF_K0);

    float sc[8][4];
    #pragma unroll
    for (int i = 0; i < 8; i++){ sc[i][0]=0.f; sc[i][1]=0.f; sc[i][2]=0.f; sc[i][3]=0.f; }
    #pragma unroll
    for (int jp = 0; jp < 4; jp++){
      #pragma unroll
      for (int kk = 0; kk < 8; kk++){
        uint32_t kb[4];
        int row = jp*16 + (lane & 15);
        int ch  = kk*2 + (lane >> 4);
        ldsm4(kb, kbase + row*256 + ((ch ^ (row & 7))*16));
        mma_bf16(sc[2*jp],   qa[kk], kb[0], kb[2]);
        mma_bf16(sc[2*jp+1], qa[kk], kb[1], kb[3]);
      }
    }

    if (jt < 8) asm volatile("cp.async.wait_group 1;" ::: "memory");  // V(jt) done
    else        asm volatile("cp.async.wait_group 0;" ::: "memory");
    __syncthreads();

    uint32_t pa[4][4];
    #pragma unroll
    for (int j = 0; j < 8; j++){
      float p0 = __expf(sc[j][0]*invsE), p1 = __expf(sc[j][1]*invsE);
      float p2 = __expf(sc[j][2]*invsE), p3 = __expf(sc[j][3]*invsE);
      rsum0 += p0 + p1; rsum1 += p2 + p3;
      int kk = j >> 1;
      if ((j & 1) == 0){ pa[kk][0] = packbf(p0,p1); pa[kk][1] = packbf(p2,p3); }
      else             { pa[kk][2] = packbf(p0,p1); pa[kk][3] = packbf(p2,p3); }
    }

    #pragma unroll
    for (int jnp = 0; jnp < 8; jnp++){
      #pragma unroll
      for (int kk = 0; kk < 4; kk++){
        uint32_t vb[4];
        int row = jnp*16 + (lane & 15);
        int ch  = kk*2 + (lane >> 4);
        ldsm4(vb, sb + AOFF_V + row*128 + ((ch ^ (row & 7))*16));
        mma_bf16(oacc[2*jnp],   pa[kk], vb[0], vb[2]);
        mma_bf16(oacc[2*jnp+1], pa[kk], vb[1], vb[3]);
      }
    }
  }

  rsum0 += __shfl_xor_sync(0xffffffffu, rsum0, 1);
  rsum0 += __shfl_xor_sync(0xffffffffu, rsum0, 2);
  rsum1 += __shfl_xor_sync(0xffffffffu, rsum1, 1);
  rsum1 += __shfl_xor_sync(0xffffffffu, rsum1, 2);
  float inv0 = 1.f/rsum0, inv1 = 1.f/rsum1;

  int g = lane >> 2, t4 = lane & 3;
  int b = bf >> 6, kk2 = bf & 63, dy = kk2 >> 3, dx = kk2 & 7;
  int nA = r0 + w*16 + g;
  int nB = nA + 8;
  int shA = nA / SWID, swA = nA - shA*SWID;
  int shB = nB / SWID, swB = nB - shB*SWID;
  size_t baseA = (size_t)b*CHW + (size_t)(shA*8 + dy)*W + (swA*8 + dx);
  size_t baseB = (size_t)b*CHW + (size_t)(shB*8 + dy)*W + (swB*8 + dx);
  #pragma unroll
  for (int jn = 0; jn < 16; jn++){
    int c0 = jn*8 + 2*t4;
    size_t giA = baseA + (size_t)c0*HW;
    size_t giB = baseB + (size_t)c0*HW;
    g_y[giA]    = x[giA]    + oacc[jn][0]*inv0;
    g_y[giA+HW] = x[giA+HW] + oacc[jn][1]*inv0;
    g_y[giB]    = x[giB]    + oacc[jn][2]*inv1;
    g_y[giB+HW] = x[giB+HW] + oacc[jn][3]*inv1;
  }
}

// ---------------- 3x3 dilated conv via tf32 mma implicit GEMM ----------------
#define C3_SMEM (7936*4)
__global__ __launch_bounds__(256) void conv3_mma_kernel(const float* __restrict__ in,
                                                        const float4* __restrict__ wp,
                                                        const float* __restrict__ bias,
                                                        float* __restrict__ out){
  int txle = blockIdx.x*16, tyle = blockIdx.y*8, b = blockIdx.z;
  extern __shared__ float sm[];
  int tid = threadIdx.x, lane = tid & 31, wm = tid >> 5;
  int t = lane & 3, g = lane >> 2;
  uint32_t sb = s2u(sm);
  float acc[16][4] = {};

  for (int chunk = 0; chunk < 4; chunk++){
    __syncthreads();
    for (int l = tid; l < 7680; l += 256){
      int ci = l / 240, r = l - ci*240, yy = r / 20, xx = r - yy*20;
      int gy = tyle + yy - 2, gx = txle + xx - 2;
      float v = 0.f;
      if (gy >= 0 && gy < H && gx >= 0 && gx < W)
        v = in[(size_t)(b*C + chunk*32 + ci)*HW + gy*W + gx];
      sm[ci*248 + yy*20 + xx] = tf32r(v);
    }
    __syncthreads();
    #pragma unroll
    for (int kk = 0; kk < 9; kk++){
      int ky = kk/3, kx = kk - ky*3;
      #pragma unroll
      for (int c8 = 0; c8 < 4; c8++){
        uint32_t ab = sb + (uint32_t)(((c8*8 + t)*248 + (wm + 2*ky)*20 + g + 2*kx)*4);
        uint32_t a0 = ldss(ab);
        uint32_t a1 = ldss(ab + 32);
        uint32_t a2 = ldss(ab + 4*248*4);
        uint32_t a3 = ldss(ab + 4*248*4 + 32);
        const float4* wrow = wp + (size_t)((kk*16 + chunk*4 + c8)*8)*32 + lane;
        #pragma unroll
        for (int jp = 0; jp < 8; jp++){
          float4 bv = __ldg(wrow + jp*32);
          mma_tf32_f4(acc[2*jp], acc[2*jp+1], a0, a1, a2, a3, bv);
        }
      }
    }
  }

  int gx0 = txle + g, gy = tyle + wm;
  #pragma unroll
  for (int j = 0; j < 16; j++){
    int co = j*8 + 2*t;
    float2 bb = *(const float2*)&bias[co];
    size_t o0 = (size_t)(b*C + co)*HW + (size_t)gy*W + gx0;
    out[o0]        = fmaxf(acc[j][0] + bb.x, 0.f);
    out[o0 + HW]   = fmaxf(acc[j][1] + bb.y, 0.f);
    out[o0 + 8]    = fmaxf(acc[j][2] + bb.x, 0.f);
    out[o0 + HW+8] = fmaxf(acc[j][3] + bb.y, 0.f);
  }
}

// ---------------- 1x1 conv via tf32 mma + bias + residual ----------------
#define C1M_SMEM (32*136*4)
__global__ __launch_bounds__(256) void conv1x1_mma_kernel(const float* __restrict__ hin,
                                                          const float4* __restrict__ wp,
                                                          const float* __restrict__ bias,
                                                          const float* __restrict__ x,
                                                          float* __restrict__ out){
  int blk = blockIdx.x;
  int b = blk / 288, hw0 = (blk - b*288)*128;
  extern __shared__ float sm[];
  int tid = threadIdx.x, lane = tid & 31, wm = tid >> 5;
  int t = lane & 3, g = lane >> 2;
  uint32_t sb = s2u(sm);
  float acc[16][4] = {};

  for (int chunk = 0; chunk < 4; chunk++){
    __syncthreads();
    for (int l = tid; l < 4096; l += 256){
      int ci = l >> 7, p = l & 127;
      sm[ci*136 + p] = tf32r(hin[(size_t)(b*C + chunk*32 + ci)*HW + hw0 + p]);
    }
    __syncthreads();
    #pragma unroll
    for (int c8 = 0; c8 < 4; c8++){
      uint32_t ab = sb + (uint32_t)(((c8*8 + t)*136 + wm*16 + g)*4);
      uint32_t a0 = ldss(ab);
      uint32_t a1 = ldss(ab + 32);
      uint32_t a2 = ldss(ab + 4*136*4);
      uint32_t a3 = ldss(ab + 4*136*4 + 32);
      const float4* wrow = wp + (size_t)((chunk*4 + c8)*8)*32 + lane;
      #pragma unroll
      for (int jp = 0; jp < 8; jp++){
        float4 bv = __ldg(wrow + jp*32);
        mma_tf32_f4(acc[2*jp], acc[2*jp+1], a0, a1, a2, a3, bv);
      }
    }
  }

  int p0 = hw0 + wm*16 + g;
  #pragma unroll
  for (int j = 0; j < 16; j++){
    int co = j*8 + 2*t;
    float2 bb = *(const float2*)&bias[co];
    size_t o0 = (size_t)(b*C + co)*HW + p0;
    out[o0]        = x[o0]        + acc[j][0] + bb.x;
    out[o0 + HW]   = x[o0 + HW]   + acc[j][1] + bb.y;
    out[o0 + 8]    = x[o0 + 8]    + acc[j][2] + bb.x;
    out[o0 + HW+8] = x[o0 + HW+8] + acc[j][3] + bb.y;
  }
}

// ---------------- launch ----------------
extern "C" void kernel_launch(void* const* d_in, const int* in_sizes, int n_in,
                              void* d_out, int out_size){
  const float* x   = (const float*)d_in[0];
  const float* wqk = (const float*)d_in[1];
  const float* w1  = (const float*)d_in[2];
  const float* b1  = (const float*)d_in[3];
  const float* w2  = (const float*)d_in[4];
  const float* b2  = (const float*)d_in[5];
  const float* w3  = (const float*)d_in[6];
  const float* b3  = (const float*)d_in[7];
  float* out = (float*)d_out;

  cudaFuncSetAttribute(prep_mma_kernel,   cudaFuncAttributeMaxDynamicSharedMemorySize, PREPM_SMEM);
  cudaFuncSetAttribute(attn_mma_kernel,   cudaFuncAttributeMaxDynamicSharedMemorySize, ATTN_SMEM);
  cudaFuncSetAttribute(conv3_mma_kernel,  cudaFuncAttributeMaxDynamicSharedMemorySize, C3_SMEM);
  cudaFuncSetAttribute(conv1x1_mma_kernel,cudaFuncAttributeMaxDynamicSharedMemorySize, C1M_SMEM);

  void *py_, *ph1_, *ph2_, *pw1_, *pw2_, *pw3_;
  cudaGetSymbolAddress(&py_,  g_y);
  cudaGetSymbolAddress(&ph1_, g_h1);
  cudaGetSymbolAddress(&ph2_, g_h2);
  cudaGetSymbolAddress(&pw1_, g_wq1);
  cudaGetSymbolAddress(&pw2_, g_wq2);
  cudaGetSymbolAddress(&pw3_, g_wq3);
  float*  py  = (float*)py_;
  float*  ph1 = (float*)ph1_;
  float*  ph2 = (float*)ph2_;
  float4* pw1 = (float4*)pw1_;
  float4* pw2 = (float4*)pw2_;
  float4* pw3 = (float4*)pw3_;

  prepack_kernel<<<320, 256>>>(w1, w2, w3, wqk);
  ln_partial_kernel<<<dim3(NB, BB), 256>>>(x);
  ln_final_kernel<<<BB, 256>>>();
  prep_mma_kernel<<<(BF*NN)/64, 256, PREPM_SMEM>>>(x);
  attn_mma_kernel<<<dim3(9, BF), 128, ATTN_SMEM>>>(x);
  conv3_mma_kernel<<<dim3(12, 24, 2), 256, C3_SMEM>>>(py,  pw1, b1, ph1);
  conv3_mma_kernel<<<dim3(12, 24, 2), 256, C3_SMEM>>>(ph1, pw2, b2, ph2);
  conv1x1_mma_kernel<<<576, 256, C1M_SMEM>>>(ph2, pw3, b3, x, out);
}